// round 11
// baseline (speedup 1.0000x reference)
#include <cuda_runtime.h>
#include <math.h>

// ---------------- problem constants ----------------
#define BB   8
#define HH   8
#define TT   1024
#define DD   512
#define DHH  64
#define FFD  2048
#define BT   8192        // B*T
#define BHH  64          // B*H

// ---------------- device scratch (no allocs allowed) ----------------
__device__ float g_qkv[3ll * BT * DD];                 // [3][BT][D]   48 MB
__device__ float g_scores[(long long)BHH * TT * TT];   // [B*H][T][T] 256 MB (scores -> probs in place)
__device__ float g_ctx[(long long)BT * DD];            // 16 MB
__device__ float g_tmp[(long long)BT * DD];            // 16 MB (h1)
__device__ float g_ff[(long long)BT * FFD];            // 64 MB
__device__ float g_outv[(long long)BT * DD];           // 16 MB
__device__ float g_outl[(long long)BT * DD];           // 16 MB
__device__ float g_w[BB * TT];
__device__ float g_mm[BB * 2];
__device__ int   g_ids[BB * TT];
__device__ float g_wl[BB * TT];

// =====================================================================
// Generic NN SGEMM: C[M,N] = alpha * A[M,K] @ B[K,N]  (+ epilogue)
// 64x64 tile, BK=16, 256 threads, 4x4 per thread. M,N % 64 == 0, K % 16 == 0.
// mode: 0 = store, 1 = relu, 2 = add residual (Res, same layout as C)
// =====================================================================
__global__ void __launch_bounds__(256) sgemm64(
    const float* __restrict__ A, int lda, long long sA,
    const float* __restrict__ Bm, int ldb, long long sB,
    float* __restrict__ C, int ldc, long long sC,
    const float* __restrict__ Res,
    int K, float alpha, int mode)
{
    int z = blockIdx.z;
    A  += (long long)z * sA;
    Bm += (long long)z * sB;
    C  += (long long)z * sC;
    if (Res) Res += (long long)z * sC;

    const int m0 = blockIdx.y * 64, n0 = blockIdx.x * 64;

    __shared__ __align__(16) float As[16][68];
    __shared__ __align__(16) float Bs[16][68];

    const int tid  = threadIdx.x;
    const int tr   = (tid >> 4) << 2;     // 0..60 step 4
    const int tc   = (tid & 15) << 2;
    const int la_r = tid >> 2;            // 0..63
    const int la_c = (tid & 3) << 2;      // 0,4,8,12
    const int lb_r = tid >> 4;            // 0..15
    const int lb_c = (tid & 15) << 2;     // 0..60

    float acc[4][4];
#pragma unroll
    for (int i = 0; i < 4; i++)
#pragma unroll
        for (int j = 0; j < 4; j++) acc[i][j] = 0.f;

    const float* Aptr = A + (long long)(m0 + la_r) * lda + la_c;
    const float* Bptr = Bm + (long long)lb_r * ldb + n0 + lb_c;

    for (int k0 = 0; k0 < K; k0 += 16) {
        float4 a4 = *(const float4*)(Aptr + k0);
        float4 b4 = *(const float4*)(Bptr + (long long)k0 * ldb);
        __syncthreads();
        As[la_c + 0][la_r] = a4.x;
        As[la_c + 1][la_r] = a4.y;
        As[la_c + 2][la_r] = a4.z;
        As[la_c + 3][la_r] = a4.w;
        *(float4*)&Bs[lb_r][lb_c] = b4;
        __syncthreads();
#pragma unroll
        for (int kk = 0; kk < 16; kk++) {
            float4 av = *(const float4*)&As[kk][tr];
            float4 bv = *(const float4*)&Bs[kk][tc];
            float a[4] = {av.x, av.y, av.z, av.w};
            float b[4] = {bv.x, bv.y, bv.z, bv.w};
#pragma unroll
            for (int i = 0; i < 4; i++)
#pragma unroll
                for (int j = 0; j < 4; j++)
                    acc[i][j] = fmaf(a[i], b[j], acc[i][j]);
        }
    }

#pragma unroll
    for (int i = 0; i < 4; i++) {
        long long rowoff = (long long)(m0 + tr + i) * ldc + n0 + tc;
#pragma unroll
        for (int j = 0; j < 4; j++) {
            float v = acc[i][j] * alpha;
            if (mode == 1)      v = v > 0.f ? v : 0.f;
            else if (mode == 2) v += Res[rowoff + j];
            C[rowoff + j] = v;
        }
    }
}

// =====================================================================
// Attention scores: S[b,h,q,k] = (1/8) * sum_d Q[b,h,q,d]*K[b,h,k,d]
// Q,K live in g_qkv[0] / g_qkv[1] as [BT][512] with head offset h*64. NT gemm.
// =====================================================================
__global__ void __launch_bounds__(256) attn_scores_k(
    const float* __restrict__ Q, const float* __restrict__ Km, float* __restrict__ S)
{
    const int z = blockIdx.z;
    const int b = z >> 3, h = z & 7;
    const float* Ab = Q  + ((long long)b * TT) * DD + h * DHH;
    const float* Bb = Km + ((long long)b * TT) * DD + h * DHH;
    float* Cb = S + (long long)z * TT * TT;

    const int m0 = blockIdx.y * 64, n0 = blockIdx.x * 64;

    __shared__ __align__(16) float As[16][68];
    __shared__ __align__(16) float Bs[16][68];

    const int tid  = threadIdx.x;
    const int tr   = (tid >> 4) << 2;
    const int tc   = (tid & 15) << 2;
    const int l_r  = tid >> 2;
    const int l_c  = (tid & 3) << 2;

    float acc[4][4];
#pragma unroll
    for (int i = 0; i < 4; i++)
#pragma unroll
        for (int j = 0; j < 4; j++) acc[i][j] = 0.f;

    const float* Ap = Ab + (long long)(m0 + l_r) * DD + l_c;
    const float* Bp = Bb + (long long)(n0 + l_r) * DD + l_c;

#pragma unroll
    for (int k0 = 0; k0 < DHH; k0 += 16) {
        float4 a4 = *(const float4*)(Ap + k0);
        float4 b4 = *(const float4*)(Bp + k0);
        __syncthreads();
        As[l_c + 0][l_r] = a4.x; As[l_c + 1][l_r] = a4.y;
        As[l_c + 2][l_r] = a4.z; As[l_c + 3][l_r] = a4.w;
        Bs[l_c + 0][l_r] = b4.x; Bs[l_c + 1][l_r] = b4.y;
        Bs[l_c + 2][l_r] = b4.z; Bs[l_c + 3][l_r] = b4.w;
        __syncthreads();
#pragma unroll
        for (int kk = 0; kk < 16; kk++) {
            float4 av = *(const float4*)&As[kk][tr];
            float4 bv = *(const float4*)&Bs[kk][tc];
            float a[4] = {av.x, av.y, av.z, av.w};
            float b[4] = {bv.x, bv.y, bv.z, bv.w};
#pragma unroll
            for (int i = 0; i < 4; i++)
#pragma unroll
                for (int j = 0; j < 4; j++)
                    acc[i][j] = fmaf(a[i], b[j], acc[i][j]);
        }
    }

#pragma unroll
    for (int i = 0; i < 4; i++) {
        long long rowoff = (long long)(m0 + tr + i) * TT + n0 + tc;
#pragma unroll
        for (int j = 0; j < 4; j++)
            Cb[rowoff + j] = acc[i][j] * 0.125f;
    }
}

// =====================================================================
// PV: ctx[b,q,h*64+n] = sum_k P[b,h,q,k] * V[b,k,h*64+n]   (N=64)
// =====================================================================
__global__ void __launch_bounds__(256) attn_pv_k(
    const float* __restrict__ P, const float* __restrict__ V, float* __restrict__ ctx)
{
    const int z = blockIdx.z;
    const int b = z >> 3, h = z & 7;
    const float* Ab = P + (long long)z * TT * TT;
    const float* Bb = V + ((long long)b * TT) * DD + h * DHH;
    float* Cb = ctx + ((long long)b * TT) * DD + h * DHH;

    const int m0 = blockIdx.y * 64;   // n0 = 0 (N=64)

    __shared__ __align__(16) float As[16][68];
    __shared__ __align__(16) float Bs[16][68];

    const int tid  = threadIdx.x;
    const int tr   = (tid >> 4) << 2;
    const int tc   = (tid & 15) << 2;
    const int la_r = tid >> 2;
    const int la_c = (tid & 3) << 2;
    const int lb_r = tid >> 4;
    const int lb_c = (tid & 15) << 2;

    float acc[4][4];
#pragma unroll
    for (int i = 0; i < 4; i++)
#pragma unroll
        for (int j = 0; j < 4; j++) acc[i][j] = 0.f;

    const float* Ap = Ab + (long long)(m0 + la_r) * TT + la_c;
    const float* Bp = Bb + (long long)lb_r * DD + lb_c;

    for (int k0 = 0; k0 < TT; k0 += 16) {
        float4 a4 = *(const float4*)(Ap + k0);
        float4 b4 = *(const float4*)(Bp + (long long)k0 * DD);
        __syncthreads();
        As[la_c + 0][la_r] = a4.x; As[la_c + 1][la_r] = a4.y;
        As[la_c + 2][la_r] = a4.z; As[la_c + 3][la_r] = a4.w;
        *(float4*)&Bs[lb_r][lb_c] = b4;
        __syncthreads();
#pragma unroll
        for (int kk = 0; kk < 16; kk++) {
            float4 av = *(const float4*)&As[kk][tr];
            float4 bv = *(const float4*)&Bs[kk][tc];
            float a[4] = {av.x, av.y, av.z, av.w};
            float b[4] = {bv.x, bv.y, bv.z, bv.w};
#pragma unroll
            for (int i = 0; i < 4; i++)
#pragma unroll
                for (int j = 0; j < 4; j++)
                    acc[i][j] = fmaf(a[i], b[j], acc[i][j]);
        }
    }

#pragma unroll
    for (int i = 0; i < 4; i++) {
        long long rowoff = (long long)(m0 + tr + i) * DD + tc;
#pragma unroll
        for (int j = 0; j < 4; j++)
            Cb[rowoff + j] = acc[i][j];
    }
}

// =====================================================================
// Row softmax over T=1024 (in place). ids != null => block-diagonal window
// mask (score -> -inf where ids differ), applied before max/exp.
// One block (256 thr) per (b,h,q) row.
// =====================================================================
__global__ void __launch_bounds__(256) softmax_rows_k(float* __restrict__ S,
                                                      const int* __restrict__ ids)
{
    const long long r = blockIdx.x;           // 0 .. B*H*T-1
    const int q  = (int)(r & (TT - 1));
    const int bh = (int)(r >> 10);
    const int b  = bh >> 3;
    float* row = S + r * TT;
    const int tid = threadIdx.x;

    __shared__ float sh[256];

    const float NEG = __int_as_float(0xff800000);   // -inf
    const int idbase = b * TT;
    const int qid = ids ? ids[idbase + q] : 0;

    float v[4];
    float mx = -3.4e38f;
#pragma unroll
    for (int i = 0; i < 4; i++) {
        int k = tid + i * 256;
        float x = row[k];
        if (ids && ids[idbase + k] != qid) x = NEG;
        v[i] = x;
        mx = fmaxf(mx, x);
    }
    sh[tid] = mx; __syncthreads();
    for (int s = 128; s > 0; s >>= 1) { if (tid < s) sh[tid] = fmaxf(sh[tid], sh[tid + s]); __syncthreads(); }
    mx = sh[0]; __syncthreads();

    float e[4];
    float sum = 0.f;
#pragma unroll
    for (int i = 0; i < 4; i++) { e[i] = expf(v[i] - mx); sum += e[i]; }
    sh[tid] = sum; __syncthreads();
    for (int s = 128; s > 0; s >>= 1) { if (tid < s) sh[tid] += sh[tid + s]; __syncthreads(); }
    const float inv = 1.f / sh[0];

#pragma unroll
    for (int i = 0; i < 4; i++) row[tid + i * 256] = e[i] * inv;
}

// =====================================================================
// Column sum (double accum): w[b,k] = (1/H) * sum_{h,q} P[b,h,q,k]
// grid (B, T/256)
// =====================================================================
__global__ void __launch_bounds__(256) colsum_k(const float* __restrict__ P,
                                                float* __restrict__ w)
{
    const int b = blockIdx.x;
    const int k = blockIdx.y * 256 + threadIdx.x;
    const float* p = P + (long long)b * HH * TT * TT + k;
    double s0 = 0, s1 = 0, s2 = 0, s3 = 0;
    for (long long i = 0; i < (long long)HH * TT; i += 4) {
        s0 += (double)p[i * TT];
        s1 += (double)p[(i + 1) * TT];
        s2 += (double)p[(i + 2) * TT];
        s3 += (double)p[(i + 3) * TT];
    }
    w[b * TT + k] = (float)(((s0 + s1) + (s2 + s3)) * (1.0 / HH));
}

// min / max per batch over T
__global__ void __launch_bounds__(256) minmax_k(const float* __restrict__ w,
                                                float* __restrict__ mm)
{
    const int b = blockIdx.x, tid = threadIdx.x;
    __shared__ float smn[256], smx[256];
    float mn = 3.4e38f, mx = -3.4e38f;
    for (int t = tid; t < TT; t += 256) {
        float x = w[b * TT + t];
        mn = fminf(mn, x); mx = fmaxf(mx, x);
    }
    smn[tid] = mn; smx[tid] = mx; __syncthreads();
    for (int s = 128; s > 0; s >>= 1) {
        if (tid < s) { smn[tid] = fminf(smn[tid], smn[tid + s]); smx[tid] = fmaxf(smx[tid], smx[tid + s]); }
        __syncthreads();
    }
    if (tid == 0) { mm[b * 2] = smn[0]; mm[b * 2 + 1] = smx[0]; }
}

// faithful sequential window-id scan (one thread per batch)
__global__ void winscan_k(const float* __restrict__ w, const float* __restrict__ mm,
                          int* __restrict__ ids)
{
    const int b = threadIdx.x;
    if (b >= BB) return;
    const float mn  = mm[b * 2];
    const float den = mm[b * 2 + 1] - mn + 1e-8f;
    const float* wb = w + b * TT;
    int* idb = ids + b * TT;

    bool cur = ((wb[0] - mn) / den) >= 0.5f;
    int start = 0, wid = 0;
    idb[0] = 0;
    for (int t = 1; t < TT; t++) {
        bool wt = ((wb[t] - mn) / den) >= 0.5f;
        if (wt != cur) {
            cur = wt;
            if (start + 1 != t) { start = t; wid++; }   // close (else: merge)
        }
        idb[t] = wid;
    }
}

// softmax over T per batch: wl = softmax(w)
__global__ void __launch_bounds__(256) softmax1d_k(const float* __restrict__ w,
                                                   float* __restrict__ wl)
{
    const int b = blockIdx.x, tid = threadIdx.x;
    __shared__ float sh[256];
    float v[4];
    float mx = -3.4e38f;
#pragma unroll
    for (int i = 0; i < 4; i++) { v[i] = w[b * TT + tid + i * 256]; mx = fmaxf(mx, v[i]); }
    sh[tid] = mx; __syncthreads();
    for (int s = 128; s > 0; s >>= 1) { if (tid < s) sh[tid] = fmaxf(sh[tid], sh[tid + s]); __syncthreads(); }
    mx = sh[0]; __syncthreads();
    float e[4], sum = 0.f;
#pragma unroll
    for (int i = 0; i < 4; i++) { e[i] = expf(v[i] - mx); sum += e[i]; }
    sh[tid] = sum; __syncthreads();
    for (int s = 128; s > 0; s >>= 1) { if (tid < s) sh[tid] += sh[tid + s]; __syncthreads(); }
    const float inv = 1.f / sh[0];
#pragma unroll
    for (int i = 0; i < 4; i++) wl[b * TT + tid + i * 256] = e[i] * inv;
}

// in-place LayerNorm over D=512 (no affine), one block per token row
__global__ void __launch_bounds__(256) ln_k(float* __restrict__ X)
{
    const long long r = blockIdx.x;
    float* row = X + r * DD;
    const int tid = threadIdx.x;
    __shared__ float sh[256];

    float x0 = row[tid], x1 = row[tid + 256];
    sh[tid] = x0 + x1; __syncthreads();
    for (int s = 128; s > 0; s >>= 1) { if (tid < s) sh[tid] += sh[tid + s]; __syncthreads(); }
    const float mean = sh[0] * (1.f / DD);
    __syncthreads();

    const float d0 = x0 - mean, d1 = x1 - mean;
    sh[tid] = d0 * d0 + d1 * d1; __syncthreads();
    for (int s = 128; s > 0; s >>= 1) { if (tid < s) sh[tid] += sh[tid + s]; __syncthreads(); }
    const float var = sh[0] * (1.f / DD);
    const float rs = 1.f / sqrtf(var + 1e-5f);
    row[tid] = d0 * rs;
    row[tid + 256] = d1 * rs;
}

// out[:, 0:T, :] = 0 ; out[:, T:2T, :] = x
__global__ void __launch_bounds__(256) outinit_k(const float* __restrict__ x,
                                                 float* __restrict__ out)
{
    const long long idx = (long long)blockIdx.x * 256 + threadIdx.x;   // B*2T*D total
    const int d = (int)(idx & (DD - 1));
    const long long rb = idx >> 9;
    const int r = (int)(rb & (2 * TT - 1));
    const int b = (int)(rb >> 11);
    out[idx] = (r < TT) ? 0.f : x[((long long)b * TT + (r - TT)) * DD + d];
}

// segmented pooling: word_tokens[b, ids[t], d] = sum over run of out_l*wl
__global__ void __launch_bounds__(512) pool_k(const float* __restrict__ outl,
                                              const float* __restrict__ wl,
                                              const int* __restrict__ ids,
                                              float* __restrict__ out)
{
    const int b = blockIdx.x, d = threadIdx.x;   // 512 threads
    __shared__ int   sids[TT];
    __shared__ float swl[TT];
    for (int t = d; t < TT; t += 512) {
        sids[t] = ids[b * TT + t];
        swl[t]  = wl[b * TT + t];
    }
    __syncthreads();

    const float* xb = outl + (long long)b * TT * DD + d;
    float acc = 0.f;
    for (int t0 = 0; t0 < TT; t0 += 16) {
        float vals[16];
#pragma unroll
        for (int u = 0; u < 16; u++) vals[u] = xb[(long long)(t0 + u) * DD];
#pragma unroll
        for (int u = 0; u < 16; u++) {
            const int t = t0 + u;
            acc = fmaf(vals[u], swl[t], acc);
            const int curid = sids[t];
            const bool flush = (t == TT - 1) || (sids[t + 1] != curid);
            if (flush) {
                out[((long long)b * 2 * TT + curid) * DD + d] = acc;
                acc = 0.f;
            }
        }
    }
}

// window_mapping[b, w, j] = (ids[b,j] == w)
__global__ void __launch_bounds__(256) mapping_k(const int* __restrict__ ids,
                                                 float* __restrict__ out2)
{
    const long long idx = (long long)blockIdx.x * 256 + threadIdx.x;   // B*T*T total
    const int j = (int)(idx & (TT - 1));
    const long long wb = idx >> 10;
    const int wrow = (int)(wb & (TT - 1));
    const int b = (int)(wb >> 10);
    out2[idx] = (ids[b * TT + j] == wrow) ? 1.f : 0.f;
}

// =====================================================================
// host
// =====================================================================
extern "C" void kernel_launch(void* const* d_in, const int* in_sizes, int n_in,
                              void* d_out, int out_size)
{
    (void)in_sizes; (void)n_in; (void)out_size;
    const float* x       = (const float*)d_in[0];
    const float* v_qkv_w = (const float*)d_in[1];
    const float* v_out_w = (const float*)d_in[2];
    const float* v_w1    = (const float*)d_in[3];
    const float* v_w2    = (const float*)d_in[4];
    const float* l_qkv_w = (const float*)d_in[5];
    const float* l_out_w = (const float*)d_in[6];
    const float* l_w1    = (const float*)d_in[7];
    const float* l_w2    = (const float*)d_in[8];
    float* out = (float*)d_out;

    float *qkv, *scores, *ctx, *tmp, *ff, *outv, *outl, *w, *mm, *wl;
    int* ids;
    cudaGetSymbolAddress((void**)&qkv,    g_qkv);
    cudaGetSymbolAddress((void**)&scores, g_scores);
    cudaGetSymbolAddress((void**)&ctx,    g_ctx);
    cudaGetSymbolAddress((void**)&tmp,    g_tmp);
    cudaGetSymbolAddress((void**)&ff,     g_ff);
    cudaGetSymbolAddress((void**)&outv,   g_outv);
    cudaGetSymbolAddress((void**)&outl,   g_outl);
    cudaGetSymbolAddress((void**)&w,      g_w);
    cudaGetSymbolAddress((void**)&mm,     g_mm);
    cudaGetSymbolAddress((void**)&ids,    g_ids);
    cudaGetSymbolAddress((void**)&wl,     g_wl);

    const dim3 blk(256);
    const long long sQKVw = (long long)DD * DD;
    const long long sQKVc = (long long)BT * DD;

    // ---------------- layer 1 (vanilla) ----------------
    sgemm64<<<dim3(DD / 64, BT / 64, 3), blk>>>(x, DD, 0, v_qkv_w, DD, sQKVw,
                                                qkv, DD, sQKVc, nullptr, DD, 1.f, 0);
    attn_scores_k<<<dim3(TT / 64, TT / 64, BHH), blk>>>(qkv, qkv + sQKVc, scores);
    softmax_rows_k<<<BHH * TT, blk>>>(scores, nullptr);
    colsum_k<<<dim3(BB, TT / 256), blk>>>(scores, w);
    minmax_k<<<BB, blk>>>(w, mm);
    winscan_k<<<1, 32>>>(w, mm, ids);
    attn_pv_k<<<dim3(1, TT / 64, BHH), blk>>>(scores, qkv + 2 * sQKVc, ctx);
    sgemm64<<<dim3(DD / 64, BT / 64, 1), blk>>>(ctx, DD, 0, v_out_w, DD, 0,
                                                tmp, DD, 0, x, DD, 1.f, 2);
    ln_k<<<BT, blk>>>(tmp);
    sgemm64<<<dim3(FFD / 64, BT / 64, 1), blk>>>(tmp, DD, 0, v_w1, FFD, 0,
                                                 ff, FFD, 0, nullptr, DD, 1.f, 1);
    sgemm64<<<dim3(DD / 64, BT / 64, 1), blk>>>(ff, FFD, 0, v_w2, DD, 0,
                                                outv, DD, 0, tmp, FFD, 1.f, 2);
    ln_k<<<BT, blk>>>(outv);

    // ---------------- layer 2 (windowed) ----------------
    sgemm64<<<dim3(DD / 64, BT / 64, 3), blk>>>(outv, DD, 0, l_qkv_w, DD, sQKVw,
                                                qkv, DD, sQKVc, nullptr, DD, 1.f, 0);
    attn_scores_k<<<dim3(TT / 64, TT / 64, BHH), blk>>>(qkv, qkv + sQKVc, scores);
    softmax_rows_k<<<BHH * TT, blk>>>(scores, ids);
    colsum_k<<<dim3(BB, TT / 256), blk>>>(scores, w);
    softmax1d_k<<<BB, blk>>>(w, wl);
    attn_pv_k<<<dim3(1, TT / 64, BHH), blk>>>(scores, qkv + 2 * sQKVc, ctx);
    sgemm64<<<dim3(DD / 64, BT / 64, 1), blk>>>(ctx, DD, 0, l_out_w, DD, 0,
                                                tmp, DD, 0, outv, DD, 1.f, 2);
    ln_k<<<BT, blk>>>(tmp);
    sgemm64<<<dim3(FFD / 64, BT / 64, 1), blk>>>(tmp, DD, 0, l_w1, FFD, 0,
                                                 ff, FFD, 0, nullptr, DD, 1.f, 1);
    sgemm64<<<dim3(DD / 64, BT / 64, 1), blk>>>(ff, FFD, 0, l_w2, DD, 0,
                                                outl, DD, 0, tmp, FFD, 1.f, 2);
    ln_k<<<BT, blk>>>(outl);

    // ---------------- outputs ----------------
    const long long n1 = (long long)BB * 2 * TT * DD;   // concat region
    outinit_k<<<(unsigned)(n1 / 256), blk>>>(x, out);
    pool_k<<<BB, 512>>>(outl, wl, ids, out);
    mapping_k<<<(unsigned)(((long long)BB * TT * TT) / 256), blk>>>(ids, out + n1);
}

// round 12
// speedup vs baseline: 1.5889x; 1.5889x over previous
#include <cuda_runtime.h>
#include <cuda_bf16.h>
#include <mma.h>
#include <math.h>

using namespace nvcuda;
typedef __nv_bfloat16 bf16;

// ---------------- problem constants ----------------
#define BB   8
#define HH   8
#define TT   1024
#define DD   512
#define DHH  64
#define FFD  2048
#define BT   8192        // B*T
#define BHH  64          // B*H

// weight offsets in the packed bf16 weight buffer
#define OFF_VQKV 0LL
#define OFF_VOUT (3LL*DD*DD)
#define OFF_VW1  (OFF_VOUT + (long long)DD*DD)
#define OFF_VW2  (OFF_VW1 + (long long)DD*FFD)
#define OFF_LQKV (OFF_VW2 + (long long)FFD*DD)
#define OFF_LOUT (OFF_LQKV + 3LL*DD*DD)
#define OFF_LW1  (OFF_LOUT + (long long)DD*DD)
#define OFF_LW2  (OFF_LW1 + (long long)DD*FFD)
#define WBF_TOTAL (OFF_LW2 + (long long)FFD*DD)

// ---------------- device scratch (no allocs allowed) ----------------
__device__ float g_qkv[3ll * BT * DD];                 // 48 MB
__device__ float g_scores[(long long)BHH * TT * TT];   // 256 MB (scores -> probs in place)
__device__ float g_ctx[(long long)BT * DD];
__device__ float g_tmp[(long long)BT * DD];
__device__ float g_ff[(long long)BT * FFD];
__device__ float g_outv[(long long)BT * DD];
__device__ float g_outl[(long long)BT * DD];
__device__ float g_w[BB * TT];
__device__ float g_mm[BB * 2];
__device__ int   g_ids[BB * TT];
__device__ float g_wl[BB * TT];

__device__ bf16 g_wbf[WBF_TOTAL];                      // 12 MB packed weights
__device__ bf16 g_xbf[(long long)BT * DD];
__device__ bf16 g_qkvbf[3ll * BT * DD];
__device__ bf16 g_probsbf[(long long)BHH * TT * TT];   // 128 MB
__device__ bf16 g_ctxbf[(long long)BT * DD];
__device__ bf16 g_tmpbf[(long long)BT * DD];
__device__ bf16 g_outvbf[(long long)BT * DD];
__device__ bf16 g_ffbf[(long long)BT * FFD];

// =====================================================================
// fp32 SGEMM (64x64 tile) — used ONLY for the threshold-critical layer-1
// Q,K projections. mode 0 store.
// =====================================================================
__global__ void __launch_bounds__(256) sgemm64(
    const float* __restrict__ A, int lda, long long sA,
    const float* __restrict__ Bm, int ldb, long long sB,
    float* __restrict__ C, int ldc, long long sC,
    int K)
{
    int z = blockIdx.z;
    A  += (long long)z * sA;
    Bm += (long long)z * sB;
    C  += (long long)z * sC;

    const int m0 = blockIdx.y * 64, n0 = blockIdx.x * 64;

    __shared__ __align__(16) float As[16][68];
    __shared__ __align__(16) float Bs[16][68];

    const int tid  = threadIdx.x;
    const int tr   = (tid >> 4) << 2;
    const int tc   = (tid & 15) << 2;
    const int la_r = tid >> 2;
    const int la_c = (tid & 3) << 2;
    const int lb_r = tid >> 4;
    const int lb_c = (tid & 15) << 2;

    float acc[4][4];
#pragma unroll
    for (int i = 0; i < 4; i++)
#pragma unroll
        for (int j = 0; j < 4; j++) acc[i][j] = 0.f;

    const float* Aptr = A + (long long)(m0 + la_r) * lda + la_c;
    const float* Bptr = Bm + (long long)lb_r * ldb + n0 + lb_c;

    for (int k0 = 0; k0 < K; k0 += 16) {
        float4 a4 = *(const float4*)(Aptr + k0);
        float4 b4 = *(const float4*)(Bptr + (long long)k0 * ldb);
        __syncthreads();
        As[la_c + 0][la_r] = a4.x;
        As[la_c + 1][la_r] = a4.y;
        As[la_c + 2][la_r] = a4.z;
        As[la_c + 3][la_r] = a4.w;
        *(float4*)&Bs[lb_r][lb_c] = b4;
        __syncthreads();
#pragma unroll
        for (int kk = 0; kk < 16; kk++) {
            float4 av = *(const float4*)&As[kk][tr];
            float4 bv = *(const float4*)&Bs[kk][tc];
            float a[4] = {av.x, av.y, av.z, av.w};
            float b[4] = {bv.x, bv.y, bv.z, bv.w};
#pragma unroll
            for (int i = 0; i < 4; i++)
#pragma unroll
                for (int j = 0; j < 4; j++)
                    acc[i][j] = fmaf(a[i], b[j], acc[i][j]);
        }
    }

#pragma unroll
    for (int i = 0; i < 4; i++) {
        long long rowoff = (long long)(m0 + tr + i) * ldc + n0 + tc;
#pragma unroll
        for (int j = 0; j < 4; j++)
            C[rowoff + j] = acc[i][j];
    }
}

// =====================================================================
// fp32 attention scores (layer 1, threshold-critical):
// S[b,h,q,k] = (1/8) sum_d Q*K
// =====================================================================
__global__ void __launch_bounds__(256) attn_scores_k(
    const float* __restrict__ Q, const float* __restrict__ Km, float* __restrict__ S)
{
    const int z = blockIdx.z;
    const int b = z >> 3, h = z & 7;
    const float* Ab = Q  + ((long long)b * TT) * DD + h * DHH;
    const float* Bb = Km + ((long long)b * TT) * DD + h * DHH;
    float* Cb = S + (long long)z * TT * TT;

    const int m0 = blockIdx.y * 64, n0 = blockIdx.x * 64;

    __shared__ __align__(16) float As[16][68];
    __shared__ __align__(16) float Bs[16][68];

    const int tid = threadIdx.x;
    const int tr  = (tid >> 4) << 2;
    const int tc  = (tid & 15) << 2;
    const int l_r = tid >> 2;
    const int l_c = (tid & 3) << 2;

    float acc[4][4];
#pragma unroll
    for (int i = 0; i < 4; i++)
#pragma unroll
        for (int j = 0; j < 4; j++) acc[i][j] = 0.f;

    const float* Ap = Ab + (long long)(m0 + l_r) * DD + l_c;
    const float* Bp = Bb + (long long)(n0 + l_r) * DD + l_c;

#pragma unroll
    for (int k0 = 0; k0 < DHH; k0 += 16) {
        float4 a4 = *(const float4*)(Ap + k0);
        float4 b4 = *(const float4*)(Bp + k0);
        __syncthreads();
        As[l_c + 0][l_r] = a4.x; As[l_c + 1][l_r] = a4.y;
        As[l_c + 2][l_r] = a4.z; As[l_c + 3][l_r] = a4.w;
        Bs[l_c + 0][l_r] = b4.x; Bs[l_c + 1][l_r] = b4.y;
        Bs[l_c + 2][l_r] = b4.z; Bs[l_c + 3][l_r] = b4.w;
        __syncthreads();
#pragma unroll
        for (int kk = 0; kk < 16; kk++) {
            float4 av = *(const float4*)&As[kk][tr];
            float4 bv = *(const float4*)&Bs[kk][tc];
            float a[4] = {av.x, av.y, av.z, av.w};
            float b[4] = {bv.x, bv.y, bv.z, bv.w};
#pragma unroll
            for (int i = 0; i < 4; i++)
#pragma unroll
                for (int j = 0; j < 4; j++)
                    acc[i][j] = fmaf(a[i], b[j], acc[i][j]);
        }
    }

#pragma unroll
    for (int i = 0; i < 4; i++) {
        long long rowoff = (long long)(m0 + tr + i) * TT + n0 + tc;
#pragma unroll
        for (int j = 0; j < 4; j++)
            Cb[rowoff + j] = acc[i][j] * 0.125f;
    }
}

// =====================================================================
// bf16 WMMA GEMM (NN): C[M,N] = A@B (+Res / relu). 128x128x32 tile,
// 8 warps (2 along M x 4 along N), warp tile 64x32.
// mode: 0 store, 1 relu, 2 += Res
// =====================================================================
__global__ void __launch_bounds__(256) bgemm_nn(
    const bf16* __restrict__ A, int lda, long long sA,
    const bf16* __restrict__ Bm, int ldb, long long sB,
    float* __restrict__ C, int ldc, long long sC,
    const float* __restrict__ Res, int K, int mode)
{
    const int z = blockIdx.z;
    A  += (long long)z * sA;
    Bm += (long long)z * sB;
    C  += (long long)z * sC;

    const int m0 = blockIdx.y * 128, n0 = blockIdx.x * 128;

    __shared__ __align__(16) bf16 As[128][40];
    __shared__ __align__(16) bf16 Bs[32][136];

    const int tid  = threadIdx.x;
    const int warp = tid >> 5;
    const int wm   = warp & 1;      // 0..1 -> 64 rows
    const int wn   = warp >> 1;     // 0..3 -> 32 cols

    wmma::fragment<wmma::accumulator, 16, 16, 16, float> acc[4][2];
    if (mode == 2) {
#pragma unroll
        for (int i = 0; i < 4; i++)
#pragma unroll
            for (int j = 0; j < 2; j++)
                wmma::load_matrix_sync(acc[i][j],
                    Res + (long long)(m0 + wm * 64 + i * 16) * ldc + n0 + wn * 32 + j * 16,
                    ldc, wmma::mem_row_major);
    } else {
#pragma unroll
        for (int i = 0; i < 4; i++)
#pragma unroll
            for (int j = 0; j < 2; j++)
                wmma::fill_fragment(acc[i][j], 0.f);
    }

    const int arow = tid >> 2,  acg = (tid & 3) * 8;
    const int brow = tid >> 4,  bcg = (tid & 15) * 8;

    for (int k0 = 0; k0 < K; k0 += 32) {
        uint4 a0 = *(const uint4*)(A + (long long)(m0 + arow)      * lda + k0 + acg);
        uint4 a1 = *(const uint4*)(A + (long long)(m0 + arow + 64) * lda + k0 + acg);
        uint4 b0 = *(const uint4*)(Bm + (long long)(k0 + brow)      * ldb + n0 + bcg);
        uint4 b1 = *(const uint4*)(Bm + (long long)(k0 + brow + 16) * ldb + n0 + bcg);
        __syncthreads();
        *(uint4*)&As[arow][acg]      = a0;
        *(uint4*)&As[arow + 64][acg] = a1;
        *(uint4*)&Bs[brow][bcg]      = b0;
        *(uint4*)&Bs[brow + 16][bcg] = b1;
        __syncthreads();
#pragma unroll
        for (int kk = 0; kk < 32; kk += 16) {
            wmma::fragment<wmma::matrix_a, 16, 16, 16, bf16, wmma::row_major> af[4];
            wmma::fragment<wmma::matrix_b, 16, 16, 16, bf16, wmma::row_major> bfr[2];
#pragma unroll
            for (int i = 0; i < 4; i++)
                wmma::load_matrix_sync(af[i], &As[wm * 64 + i * 16][kk], 40);
#pragma unroll
            for (int j = 0; j < 2; j++)
                wmma::load_matrix_sync(bfr[j], &Bs[kk][wn * 32 + j * 16], 136);
#pragma unroll
            for (int i = 0; i < 4; i++)
#pragma unroll
                for (int j = 0; j < 2; j++)
                    wmma::mma_sync(acc[i][j], af[i], bfr[j], acc[i][j]);
        }
    }

#pragma unroll
    for (int i = 0; i < 4; i++)
#pragma unroll
        for (int j = 0; j < 2; j++) {
            if (mode == 1) {
#pragma unroll
                for (int e = 0; e < acc[i][j].num_elements; e++)
                    acc[i][j].x[e] = fmaxf(acc[i][j].x[e], 0.f);
            }
            wmma::store_matrix_sync(
                C + (long long)(m0 + wm * 64 + i * 16) * ldc + n0 + wn * 32 + j * 16,
                acc[i][j], ldc, wmma::mem_row_major);
        }
}

// =====================================================================
// bf16 WMMA scores (layer 2, NT): S = 0.125 * Q @ K^T, per (b,h)
// =====================================================================
__global__ void __launch_bounds__(256) bscores(
    const bf16* __restrict__ Q, const bf16* __restrict__ Kv, float* __restrict__ S)
{
    const int z = blockIdx.z;
    const int b = z >> 3, h = z & 7;
    const bf16* Ab = Q  + ((long long)b * TT) * DD + h * DHH;
    const bf16* Bb = Kv + ((long long)b * TT) * DD + h * DHH;
    float* Cb = S + (long long)z * TT * TT;

    const int m0 = blockIdx.y * 128, n0 = blockIdx.x * 128;

    __shared__ __align__(16) bf16 As[128][40];
    __shared__ __align__(16) bf16 Ks[128][40];

    const int tid  = threadIdx.x;
    const int warp = tid >> 5;
    const int wm   = warp & 1;
    const int wn   = warp >> 1;

    wmma::fragment<wmma::accumulator, 16, 16, 16, float> acc[4][2];
#pragma unroll
    for (int i = 0; i < 4; i++)
#pragma unroll
        for (int j = 0; j < 2; j++)
            wmma::fill_fragment(acc[i][j], 0.f);

    const int arow = tid >> 2, acg = (tid & 3) * 8;

#pragma unroll
    for (int k0 = 0; k0 < DHH; k0 += 32) {
        uint4 a0 = *(const uint4*)(Ab + (long long)(m0 + arow)      * DD + k0 + acg);
        uint4 a1 = *(const uint4*)(Ab + (long long)(m0 + arow + 64) * DD + k0 + acg);
        uint4 b0 = *(const uint4*)(Bb + (long long)(n0 + arow)      * DD + k0 + acg);
        uint4 b1 = *(const uint4*)(Bb + (long long)(n0 + arow + 64) * DD + k0 + acg);
        __syncthreads();
        *(uint4*)&As[arow][acg]      = a0;
        *(uint4*)&As[arow + 64][acg] = a1;
        *(uint4*)&Ks[arow][acg]      = b0;
        *(uint4*)&Ks[arow + 64][acg] = b1;
        __syncthreads();
#pragma unroll
        for (int kk = 0; kk < 32; kk += 16) {
            wmma::fragment<wmma::matrix_a, 16, 16, 16, bf16, wmma::row_major> af[4];
            wmma::fragment<wmma::matrix_b, 16, 16, 16, bf16, wmma::col_major> bfr[2];
#pragma unroll
            for (int i = 0; i < 4; i++)
                wmma::load_matrix_sync(af[i], &As[wm * 64 + i * 16][kk], 40);
#pragma unroll
            for (int j = 0; j < 2; j++)
                wmma::load_matrix_sync(bfr[j], &Ks[wn * 32 + j * 16][kk], 40);
#pragma unroll
            for (int i = 0; i < 4; i++)
#pragma unroll
                for (int j = 0; j < 2; j++)
                    wmma::mma_sync(acc[i][j], af[i], bfr[j], acc[i][j]);
        }
    }

#pragma unroll
    for (int i = 0; i < 4; i++)
#pragma unroll
        for (int j = 0; j < 2; j++) {
#pragma unroll
            for (int e = 0; e < acc[i][j].num_elements; e++)
                acc[i][j].x[e] *= 0.125f;
            wmma::store_matrix_sync(
                Cb + (long long)(m0 + wm * 64 + i * 16) * TT + n0 + wn * 32 + j * 16,
                acc[i][j], TT, wmma::mem_row_major);
        }
}

// =====================================================================
// bf16 WMMA PV: ctx[b,q,h*64+n] = P @ V.  128x64x32 tile, 8 warps
// (4 along M x 2 along N), warp tile 32x32.
// =====================================================================
__global__ void __launch_bounds__(256) bpv(
    const bf16* __restrict__ P, const bf16* __restrict__ V, float* __restrict__ ctx)
{
    const int z = blockIdx.y;
    const int b = z >> 3, h = z & 7;
    const bf16* Ab = P + (long long)z * TT * TT;
    const bf16* Bb = V + ((long long)b * TT) * DD + h * DHH;
    float* Cb = ctx + ((long long)b * TT) * DD + h * DHH;

    const int m0 = blockIdx.x * 128;

    __shared__ __align__(16) bf16 As[128][40];
    __shared__ __align__(16) bf16 Bs[32][72];

    const int tid  = threadIdx.x;
    const int warp = tid >> 5;
    const int wm   = warp & 3;      // 0..3 -> 32 rows
    const int wn   = warp >> 2;     // 0..1 -> 32 cols

    wmma::fragment<wmma::accumulator, 16, 16, 16, float> acc[2][2];
#pragma unroll
    for (int i = 0; i < 2; i++)
#pragma unroll
        for (int j = 0; j < 2; j++)
            wmma::fill_fragment(acc[i][j], 0.f);

    const int arow = tid >> 2, acg = (tid & 3) * 8;
    const int brow = tid >> 3, bcg = (tid & 7) * 8;

    for (int k0 = 0; k0 < TT; k0 += 32) {
        uint4 a0 = *(const uint4*)(Ab + (long long)(m0 + arow)      * TT + k0 + acg);
        uint4 a1 = *(const uint4*)(Ab + (long long)(m0 + arow + 64) * TT + k0 + acg);
        uint4 b0 = *(const uint4*)(Bb + (long long)(k0 + brow) * DD + bcg);
        __syncthreads();
        *(uint4*)&As[arow][acg]      = a0;
        *(uint4*)&As[arow + 64][acg] = a1;
        *(uint4*)&Bs[brow][bcg]      = b0;
        __syncthreads();
#pragma unroll
        for (int kk = 0; kk < 32; kk += 16) {
            wmma::fragment<wmma::matrix_a, 16, 16, 16, bf16, wmma::row_major> af[2];
            wmma::fragment<wmma::matrix_b, 16, 16, 16, bf16, wmma::row_major> bfr[2];
#pragma unroll
            for (int i = 0; i < 2; i++)
                wmma::load_matrix_sync(af[i], &As[wm * 32 + i * 16][kk], 40);
#pragma unroll
            for (int j = 0; j < 2; j++)
                wmma::load_matrix_sync(bfr[j], &Bs[kk][wn * 32 + j * 16], 72);
#pragma unroll
            for (int i = 0; i < 2; i++)
#pragma unroll
                for (int j = 0; j < 2; j++)
                    wmma::mma_sync(acc[i][j], af[i], bfr[j], acc[i][j]);
        }
    }

#pragma unroll
    for (int i = 0; i < 2; i++)
#pragma unroll
        for (int j = 0; j < 2; j++)
            wmma::store_matrix_sync(
                Cb + (long long)(m0 + wm * 32 + i * 16) * DD + wn * 32 + j * 16,
                acc[i][j], DD, wmma::mem_row_major);
}

// =====================================================================
// Row softmax over T=1024 (in place, fp32) + bf16 copy of probs.
// ids != null => block-diagonal window mask.
// =====================================================================
__global__ void __launch_bounds__(256) softmax_rows_k(float* __restrict__ S,
                                                      const int* __restrict__ ids,
                                                      bf16* __restrict__ Pbf)
{
    const long long r = blockIdx.x;
    const int q  = (int)(r & (TT - 1));
    const int bh = (int)(r >> 10);
    const int b  = bh >> 3;
    float* row = S + r * TT;
    bf16*  rbf = Pbf + r * TT;
    const int tid = threadIdx.x;

    __shared__ float sh[256];

    const float NEG = __int_as_float(0xff800000);
    const int idbase = b * TT;
    const int qid = ids ? ids[idbase + q] : 0;

    float v[4];
    float mx = -3.4e38f;
#pragma unroll
    for (int i = 0; i < 4; i++) {
        int k = tid + i * 256;
        float x = row[k];
        if (ids && ids[idbase + k] != qid) x = NEG;
        v[i] = x;
        mx = fmaxf(mx, x);
    }
    sh[tid] = mx; __syncthreads();
    for (int s = 128; s > 0; s >>= 1) { if (tid < s) sh[tid] = fmaxf(sh[tid], sh[tid + s]); __syncthreads(); }
    mx = sh[0]; __syncthreads();

    float e[4];
    float sum = 0.f;
#pragma unroll
    for (int i = 0; i < 4; i++) { e[i] = expf(v[i] - mx); sum += e[i]; }
    sh[tid] = sum; __syncthreads();
    for (int s = 128; s > 0; s >>= 1) { if (tid < s) sh[tid] += sh[tid + s]; __syncthreads(); }
    const float inv = 1.f / sh[0];

#pragma unroll
    for (int i = 0; i < 4; i++) {
        float p = e[i] * inv;
        row[tid + i * 256] = p;
        rbf[tid + i * 256] = __float2bfloat16(p);
    }
}

// column sum (double accum): w[b,k] = (1/H) sum_{h,q} P[b,h,q,k]
__global__ void __launch_bounds__(256) colsum_k(const float* __restrict__ P,
                                                float* __restrict__ w)
{
    const int b = blockIdx.x;
    const int k = blockIdx.y * 256 + threadIdx.x;
    const float* p = P + (long long)b * HH * TT * TT + k;
    double s0 = 0, s1 = 0, s2 = 0, s3 = 0;
    for (long long i = 0; i < (long long)HH * TT; i += 4) {
        s0 += (double)p[i * TT];
        s1 += (double)p[(i + 1) * TT];
        s2 += (double)p[(i + 2) * TT];
        s3 += (double)p[(i + 3) * TT];
    }
    w[b * TT + k] = (float)(((s0 + s1) + (s2 + s3)) * (1.0 / HH));
}

__global__ void __launch_bounds__(256) minmax_k(const float* __restrict__ w,
                                                float* __restrict__ mm)
{
    const int b = blockIdx.x, tid = threadIdx.x;
    __shared__ float smn[256], smx[256];
    float mn = 3.4e38f, mx = -3.4e38f;
    for (int t = tid; t < TT; t += 256) {
        float x = w[b * TT + t];
        mn = fminf(mn, x); mx = fmaxf(mx, x);
    }
    smn[tid] = mn; smx[tid] = mx; __syncthreads();
    for (int s = 128; s > 0; s >>= 1) {
        if (tid < s) { smn[tid] = fminf(smn[tid], smn[tid + s]); smx[tid] = fmaxf(smx[tid], smx[tid + s]); }
        __syncthreads();
    }
    if (tid == 0) { mm[b * 2] = smn[0]; mm[b * 2 + 1] = smx[0]; }
}

__global__ void winscan_k(const float* __restrict__ w, const float* __restrict__ mm,
                          int* __restrict__ ids)
{
    const int b = threadIdx.x;
    if (b >= BB) return;
    const float mn  = mm[b * 2];
    const float den = mm[b * 2 + 1] - mn + 1e-8f;
    const float* wb = w + b * TT;
    int* idb = ids + b * TT;

    bool cur = ((wb[0] - mn) / den) >= 0.5f;
    int start = 0, wid = 0;
    idb[0] = 0;
    for (int t = 1; t < TT; t++) {
        bool wt = ((wb[t] - mn) / den) >= 0.5f;
        if (wt != cur) {
            cur = wt;
            if (start + 1 != t) { start = t; wid++; }
        }
        idb[t] = wid;
    }
}

__global__ void __launch_bounds__(256) softmax1d_k(const float* __restrict__ w,
                                                   float* __restrict__ wl)
{
    const int b = blockIdx.x, tid = threadIdx.x;
    __shared__ float sh[256];
    float v[4];
    float mx = -3.4e38f;
#pragma unroll
    for (int i = 0; i < 4; i++) { v[i] = w[b * TT + tid + i * 256]; mx = fmaxf(mx, v[i]); }
    sh[tid] = mx; __syncthreads();
    for (int s = 128; s > 0; s >>= 1) { if (tid < s) sh[tid] = fmaxf(sh[tid], sh[tid + s]); __syncthreads(); }
    mx = sh[0]; __syncthreads();
    float e[4], sum = 0.f;
#pragma unroll
    for (int i = 0; i < 4; i++) { e[i] = expf(v[i] - mx); sum += e[i]; }
    sh[tid] = sum; __syncthreads();
    for (int s = 128; s > 0; s >>= 1) { if (tid < s) sh[tid] += sh[tid + s]; __syncthreads(); }
    const float inv = 1.f / sh[0];
#pragma unroll
    for (int i = 0; i < 4; i++) wl[b * TT + tid + i * 256] = e[i] * inv;
}

// in-place LayerNorm over D=512 + optional bf16 dual write
__global__ void __launch_bounds__(256) ln_k(float* __restrict__ X, bf16* __restrict__ Xbf)
{
    const long long r = blockIdx.x;
    float* row = X + r * DD;
    const int tid = threadIdx.x;
    __shared__ float sh[256];

    float x0 = row[tid], x1 = row[tid + 256];
    sh[tid] = x0 + x1; __syncthreads();
    for (int s = 128; s > 0; s >>= 1) { if (tid < s) sh[tid] += sh[tid + s]; __syncthreads(); }
    const float mean = sh[0] * (1.f / DD);
    __syncthreads();

    const float d0 = x0 - mean, d1 = x1 - mean;
    sh[tid] = d0 * d0 + d1 * d1; __syncthreads();
    for (int s = 128; s > 0; s >>= 1) { if (tid < s) sh[tid] += sh[tid + s]; __syncthreads(); }
    const float var = sh[0] * (1.f / DD);
    const float rs = 1.f / sqrtf(var + 1e-5f);
    const float y0 = d0 * rs, y1 = d1 * rs;
    row[tid] = y0;
    row[tid + 256] = y1;
    if (Xbf) {
        Xbf[r * DD + tid]       = __float2bfloat16(y0);
        Xbf[r * DD + tid + 256] = __float2bfloat16(y1);
    }
}

// float -> bf16 conversion, 4 elems/thread (n % 1024 == 0)
__global__ void __launch_bounds__(256) f2bf_k(const float* __restrict__ src,
                                              bf16* __restrict__ dst, long long n)
{
    const long long i = ((long long)blockIdx.x * 256 + threadIdx.x) * 4;
    if (i >= n) return;
    float4 v = *(const float4*)(src + i);
    __nv_bfloat162 p0, p1;
    p0.x = __float2bfloat16(v.x); p0.y = __float2bfloat16(v.y);
    p1.x = __float2bfloat16(v.z); p1.y = __float2bfloat16(v.w);
    *(__nv_bfloat162*)(dst + i)     = p0;
    *(__nv_bfloat162*)(dst + i + 2) = p1;
}

// out[:, 0:T, :] = 0 ; out[:, T:2T, :] = x
__global__ void __launch_bounds__(256) outinit_k(const float* __restrict__ x,
                                                 float* __restrict__ out)
{
    const long long idx = (long long)blockIdx.x * 256 + threadIdx.x;
    const int d = (int)(idx & (DD - 1));
    const long long rb = idx >> 9;
    const int r = (int)(rb & (2 * TT - 1));
    const int b = (int)(rb >> 11);
    out[idx] = (r < TT) ? 0.f : x[((long long)b * TT + (r - TT)) * DD + d];
}

// segmented pooling
__global__ void __launch_bounds__(512) pool_k(const float* __restrict__ outl,
                                              const float* __restrict__ wl,
                                              const int* __restrict__ ids,
                                              float* __restrict__ out)
{
    const int b = blockIdx.x, d = threadIdx.x;
    __shared__ int   sids[TT];
    __shared__ float swl[TT];
    for (int t = d; t < TT; t += 512) {
        sids[t] = ids[b * TT + t];
        swl[t]  = wl[b * TT + t];
    }
    __syncthreads();

    const float* xb = outl + (long long)b * TT * DD + d;
    float acc = 0.f;
    for (int t0 = 0; t0 < TT; t0 += 16) {
        float vals[16];
#pragma unroll
        for (int u = 0; u < 16; u++) vals[u] = xb[(long long)(t0 + u) * DD];
#pragma unroll
        for (int u = 0; u < 16; u++) {
            const int t = t0 + u;
            acc = fmaf(vals[u], swl[t], acc);
            const int curid = sids[t];
            const bool flush = (t == TT - 1) || (sids[t + 1] != curid);
            if (flush) {
                out[((long long)b * 2 * TT + curid) * DD + d] = acc;
                acc = 0.f;
            }
        }
    }
}

__global__ void __launch_bounds__(256) mapping_k(const int* __restrict__ ids,
                                                 float* __restrict__ out2)
{
    const long long idx = (long long)blockIdx.x * 256 + threadIdx.x;
    const int j = (int)(idx & (TT - 1));
    const long long wb = idx >> 10;
    const int wrow = (int)(wb & (TT - 1));
    const int b = (int)(wb >> 10);
    out2[idx] = (ids[b * TT + j] == wrow) ? 1.f : 0.f;
}

// =====================================================================
// host
// =====================================================================
extern "C" void kernel_launch(void* const* d_in, const int* in_sizes, int n_in,
                              void* d_out, int out_size)
{
    (void)in_sizes; (void)n_in; (void)out_size;
    const float* x       = (const float*)d_in[0];
    const float* v_qkv_w = (const float*)d_in[1];
    const float* v_out_w = (const float*)d_in[2];
    const float* v_w1    = (const float*)d_in[3];
    const float* v_w2    = (const float*)d_in[4];
    const float* l_qkv_w = (const float*)d_in[5];
    const float* l_out_w = (const float*)d_in[6];
    const float* l_w1    = (const float*)d_in[7];
    const float* l_w2    = (const float*)d_in[8];
    float* out = (float*)d_out;

    float *qkv, *scores, *ctx, *tmp, *ff, *outv, *outl, *w, *mm, *wl;
    int* ids;
    bf16 *wbf, *xbf, *qkvbf, *probsbf, *ctxbf, *tmpbf, *outvbf, *ffbf;
    cudaGetSymbolAddress((void**)&qkv,    g_qkv);
    cudaGetSymbolAddress((void**)&scores, g_scores);
    cudaGetSymbolAddress((void**)&ctx,    g_ctx);
    cudaGetSymbolAddress((void**)&tmp,    g_tmp);
    cudaGetSymbolAddress((void**)&ff,     g_ff);
    cudaGetSymbolAddress((void**)&outv,   g_outv);
    cudaGetSymbolAddress((void**)&outl,   g_outl);
    cudaGetSymbolAddress((void**)&w,      g_w);
    cudaGetSymbolAddress((void**)&mm,     g_mm);
    cudaGetSymbolAddress((void**)&ids,    g_ids);
    cudaGetSymbolAddress((void**)&wl,     g_wl);
    cudaGetSymbolAddress((void**)&wbf,    g_wbf);
    cudaGetSymbolAddress((void**)&xbf,    g_xbf);
    cudaGetSymbolAddress((void**)&qkvbf,  g_qkvbf);
    cudaGetSymbolAddress((void**)&probsbf,g_probsbf);
    cudaGetSymbolAddress((void**)&ctxbf,  g_ctxbf);
    cudaGetSymbolAddress((void**)&tmpbf,  g_tmpbf);
    cudaGetSymbolAddress((void**)&outvbf, g_outvbf);
    cudaGetSymbolAddress((void**)&ffbf,   g_ffbf);

    const dim3 blk(256);
    const long long sQKVw = (long long)DD * DD;
    const long long sQKVc = (long long)BT * DD;

    // ---- weight + input conversions ----
    auto cvt = [&](const float* s, bf16* d, long long n) {
        f2bf_k<<<(unsigned)((n + 1023) / 1024), blk>>>(s, d, n);
    };
    cvt(v_qkv_w, wbf + OFF_VQKV, 3LL * DD * DD);
    cvt(v_out_w, wbf + OFF_VOUT, (long long)DD * DD);
    cvt(v_w1,    wbf + OFF_VW1,  (long long)DD * FFD);
    cvt(v_w2,    wbf + OFF_VW2,  (long long)FFD * DD);
    cvt(l_qkv_w, wbf + OFF_LQKV, 3LL * DD * DD);
    cvt(l_out_w, wbf + OFF_LOUT, (long long)DD * DD);
    cvt(l_w1,    wbf + OFF_LW1,  (long long)DD * FFD);
    cvt(l_w2,    wbf + OFF_LW2,  (long long)FFD * DD);
    cvt(x, xbf, sQKVc);

    // ---------------- layer 1 (vanilla) ----------------
    // Q,K in fp32 (threshold-critical)
    sgemm64<<<dim3(DD / 64, BT / 64, 2), blk>>>(x, DD, 0, v_qkv_w, DD, sQKVw,
                                                qkv, DD, sQKVc, DD);
    // V in bf16
    bgemm_nn<<<dim3(DD / 128, BT / 128, 1), blk>>>(xbf, DD, 0,
                                                   wbf + OFF_VQKV + 2 * sQKVw, DD, 0,
                                                   qkv + 2 * sQKVc, DD, 0, nullptr, DD, 0);
    attn_scores_k<<<dim3(TT / 64, TT / 64, BHH), blk>>>(qkv, qkv + sQKVc, scores);
    softmax_rows_k<<<BHH * TT, blk>>>(scores, nullptr, probsbf);
    colsum_k<<<dim3(BB, TT / 256), blk>>>(scores, w);
    minmax_k<<<BB, blk>>>(w, mm);
    winscan_k<<<1, 32>>>(w, mm, ids);
    cvt(qkv + 2 * sQKVc, qkvbf + 2 * sQKVc, sQKVc);
    bpv<<<dim3(TT / 128, BHH), blk>>>(probsbf, qkvbf + 2 * sQKVc, ctx);
    cvt(ctx, ctxbf, sQKVc);
    bgemm_nn<<<dim3(DD / 128, BT / 128, 1), blk>>>(ctxbf, DD, 0, wbf + OFF_VOUT, DD, 0,
                                                   tmp, DD, 0, x, DD, 2);
    ln_k<<<BT, blk>>>(tmp, tmpbf);
    bgemm_nn<<<dim3(FFD / 128, BT / 128, 1), blk>>>(tmpbf, DD, 0, wbf + OFF_VW1, FFD, 0,
                                                    ff, FFD, 0, nullptr, DD, 1);
    cvt(ff, ffbf, (long long)BT * FFD);
    bgemm_nn<<<dim3(DD / 128, BT / 128, 1), blk>>>(ffbf, FFD, 0, wbf + OFF_VW2, DD, 0,
                                                   outv, DD, 0, tmp, FFD, 2);
    ln_k<<<BT, blk>>>(outv, outvbf);

    // ---------------- layer 2 (windowed, all bf16) ----------------
    bgemm_nn<<<dim3(DD / 128, BT / 128, 3), blk>>>(outvbf, DD, 0, wbf + OFF_LQKV, DD, sQKVw,
                                                   qkv, DD, sQKVc, nullptr, DD, 0);
    cvt(qkv, qkvbf, 3 * sQKVc);
    bscores<<<dim3(TT / 128, TT / 128, BHH), blk>>>(qkvbf, qkvbf + sQKVc, scores);
    softmax_rows_k<<<BHH * TT, blk>>>(scores, ids, probsbf);
    colsum_k<<<dim3(BB, TT / 256), blk>>>(scores, w);
    softmax1d_k<<<BB, blk>>>(w, wl);
    bpv<<<dim3(TT / 128, BHH), blk>>>(probsbf, qkvbf + 2 * sQKVc, ctx);
    cvt(ctx, ctxbf, sQKVc);
    bgemm_nn<<<dim3(DD / 128, BT / 128, 1), blk>>>(ctxbf, DD, 0, wbf + OFF_LOUT, DD, 0,
                                                   tmp, DD, 0, outv, DD, 2);
    ln_k<<<BT, blk>>>(tmp, tmpbf);
    bgemm_nn<<<dim3(FFD / 128, BT / 128, 1), blk>>>(tmpbf, DD, 0, wbf + OFF_LW1, FFD, 0,
                                                    ff, FFD, 0, nullptr, DD, 1);
    cvt(ff, ffbf, (long long)BT * FFD);
    bgemm_nn<<<dim3(DD / 128, BT / 128, 1), blk>>>(ffbf, FFD, 0, wbf + OFF_LW2, DD, 0,
                                                   outl, DD, 0, tmp, FFD, 2);
    ln_k<<<BT, blk>>>(outl, nullptr);

    // ---------------- outputs ----------------
    const long long n1 = (long long)BB * 2 * TT * DD;
    outinit_k<<<(unsigned)(n1 / 256), blk>>>(x, out);
    pool_k<<<BB, 512>>>(outl, wl, ids, out);
    mapping_k<<<(unsigned)(((long long)BB * TT * TT) / 256), blk>>>(ids, out + n1);
}

// round 13
// speedup vs baseline: 1.5908x; 1.0012x over previous
#include <cuda_runtime.h>
#include <cuda_bf16.h>
#include <mma.h>
#include <math.h>

using namespace nvcuda;
typedef __nv_bfloat16 bf16;

// ---------------- problem constants ----------------
#define BB   8
#define HH   8
#define TT   1024
#define DD   512
#define DHH  64
#define FFD  2048
#define BT   8192        // B*T
#define BHH  64          // B*H

// weight offsets in the packed bf16 weight buffer
#define OFF_VQKV 0LL
#define OFF_VOUT (3LL*DD*DD)
#define OFF_VW1  (OFF_VOUT + (long long)DD*DD)
#define OFF_VW2  (OFF_VW1 + (long long)DD*FFD)
#define OFF_LQKV (OFF_VW2 + (long long)FFD*DD)
#define OFF_LOUT (OFF_LQKV + 3LL*DD*DD)
#define OFF_LW1  (OFF_LOUT + (long long)DD*DD)
#define OFF_LW2  (OFF_LW1 + (long long)DD*FFD)
#define WBF_TOTAL (OFF_LW2 + (long long)FFD*DD)

// ---------------- device scratch (no allocs allowed) ----------------
__device__ float g_qkv[3ll * BT * DD];                 // 48 MB
__device__ float g_scores[(long long)BHH * TT * TT];   // 256 MB (scores -> probs in place)
__device__ float g_ctx[(long long)BT * DD];
__device__ float g_tmp[(long long)BT * DD];
__device__ float g_ff[(long long)BT * FFD];
__device__ float g_outv[(long long)BT * DD];
__device__ float g_outl[(long long)BT * DD];
__device__ float g_w[BB * TT];
__device__ float g_mm[BB * 2];
__device__ int   g_ids[BB * TT];
__device__ float g_wl[BB * TT];

__device__ bf16 g_wbf[WBF_TOTAL];                      // 12 MB packed weights
__device__ bf16 g_xbf[(long long)BT * DD];
__device__ bf16 g_qkvbf[3ll * BT * DD];
__device__ bf16 g_probsbf[(long long)BHH * TT * TT];   // 128 MB
__device__ bf16 g_ctxbf[(long long)BT * DD];
__device__ bf16 g_tmpbf[(long long)BT * DD];
__device__ bf16 g_outvbf[(long long)BT * DD];
__device__ bf16 g_ffbf[(long long)BT * FFD];

// =====================================================================
// fp32 SGEMM (64x64 tile) — used ONLY for the threshold-critical layer-1
// Q,K projections. mode 0 store.
// =====================================================================
__global__ void __launch_bounds__(256) sgemm64(
    const float* __restrict__ A, int lda, long long sA,
    const float* __restrict__ Bm, int ldb, long long sB,
    float* __restrict__ C, int ldc, long long sC,
    int K)
{
    int z = blockIdx.z;
    A  += (long long)z * sA;
    Bm += (long long)z * sB;
    C  += (long long)z * sC;

    const int m0 = blockIdx.y * 64, n0 = blockIdx.x * 64;

    __shared__ __align__(16) float As[16][68];
    __shared__ __align__(16) float Bs[16][68];

    const int tid  = threadIdx.x;
    const int tr   = (tid >> 4) << 2;
    const int tc   = (tid & 15) << 2;
    const int la_r = tid >> 2;
    const int la_c = (tid & 3) << 2;
    const int lb_r = tid >> 4;
    const int lb_c = (tid & 15) << 2;

    float acc[4][4];
#pragma unroll
    for (int i = 0; i < 4; i++)
#pragma unroll
        for (int j = 0; j < 4; j++) acc[i][j] = 0.f;

    const float* Aptr = A + (long long)(m0 + la_r) * lda + la_c;
    const float* Bptr = Bm + (long long)lb_r * ldb + n0 + lb_c;

    for (int k0 = 0; k0 < K; k0 += 16) {
        float4 a4 = *(const float4*)(Aptr + k0);
        float4 b4 = *(const float4*)(Bptr + (long long)k0 * ldb);
        __syncthreads();
        As[la_c + 0][la_r] = a4.x;
        As[la_c + 1][la_r] = a4.y;
        As[la_c + 2][la_r] = a4.z;
        As[la_c + 3][la_r] = a4.w;
        *(float4*)&Bs[lb_r][lb_c] = b4;
        __syncthreads();
#pragma unroll
        for (int kk = 0; kk < 16; kk++) {
            float4 av = *(const float4*)&As[kk][tr];
            float4 bv = *(const float4*)&Bs[kk][tc];
            float a[4] = {av.x, av.y, av.z, av.w};
            float b[4] = {bv.x, bv.y, bv.z, bv.w};
#pragma unroll
            for (int i = 0; i < 4; i++)
#pragma unroll
                for (int j = 0; j < 4; j++)
                    acc[i][j] = fmaf(a[i], b[j], acc[i][j]);
        }
    }

#pragma unroll
    for (int i = 0; i < 4; i++) {
        long long rowoff = (long long)(m0 + tr + i) * ldc + n0 + tc;
#pragma unroll
        for (int j = 0; j < 4; j++)
            C[rowoff + j] = acc[i][j];
    }
}

// =====================================================================
// fp32 attention scores (layer 1, threshold-critical):
// S[b,h,q,k] = (1/8) sum_d Q*K
// =====================================================================
__global__ void __launch_bounds__(256) attn_scores_k(
    const float* __restrict__ Q, const float* __restrict__ Km, float* __restrict__ S)
{
    const int z = blockIdx.z;
    const int b = z >> 3, h = z & 7;
    const float* Ab = Q  + ((long long)b * TT) * DD + h * DHH;
    const float* Bb = Km + ((long long)b * TT) * DD + h * DHH;
    float* Cb = S + (long long)z * TT * TT;

    const int m0 = blockIdx.y * 64, n0 = blockIdx.x * 64;

    __shared__ __align__(16) float As[16][68];
    __shared__ __align__(16) float Bs[16][68];

    const int tid = threadIdx.x;
    const int tr  = (tid >> 4) << 2;
    const int tc  = (tid & 15) << 2;
    const int l_r = tid >> 2;
    const int l_c = (tid & 3) << 2;

    float acc[4][4];
#pragma unroll
    for (int i = 0; i < 4; i++)
#pragma unroll
        for (int j = 0; j < 4; j++) acc[i][j] = 0.f;

    const float* Ap = Ab + (long long)(m0 + l_r) * DD + l_c;
    const float* Bp = Bb + (long long)(n0 + l_r) * DD + l_c;

#pragma unroll
    for (int k0 = 0; k0 < DHH; k0 += 16) {
        float4 a4 = *(const float4*)(Ap + k0);
        float4 b4 = *(const float4*)(Bp + k0);
        __syncthreads();
        As[l_c + 0][l_r] = a4.x; As[l_c + 1][l_r] = a4.y;
        As[l_c + 2][l_r] = a4.z; As[l_c + 3][l_r] = a4.w;
        Bs[l_c + 0][l_r] = b4.x; Bs[l_c + 1][l_r] = b4.y;
        Bs[l_c + 2][l_r] = b4.z; Bs[l_c + 3][l_r] = b4.w;
        __syncthreads();
#pragma unroll
        for (int kk = 0; kk < 16; kk++) {
            float4 av = *(const float4*)&As[kk][tr];
            float4 bv = *(const float4*)&Bs[kk][tc];
            float a[4] = {av.x, av.y, av.z, av.w};
            float b[4] = {bv.x, bv.y, bv.z, bv.w};
#pragma unroll
            for (int i = 0; i < 4; i++)
#pragma unroll
                for (int j = 0; j < 4; j++)
                    acc[i][j] = fmaf(a[i], b[j], acc[i][j]);
        }
    }

#pragma unroll
    for (int i = 0; i < 4; i++) {
        long long rowoff = (long long)(m0 + tr + i) * TT + n0 + tc;
#pragma unroll
        for (int j = 0; j < 4; j++)
            Cb[rowoff + j] = acc[i][j] * 0.125f;
    }
}

// =====================================================================
// bf16 WMMA GEMM (NN): C[M,N] = A@B (+Res / relu). 128x128x32 tile,
// 8 warps (2 along M x 4 along N), warp tile 64x32.
// mode: 0 store, 1 relu, 2 += Res
// =====================================================================
__global__ void __launch_bounds__(256) bgemm_nn(
    const bf16* __restrict__ A, int lda, long long sA,
    const bf16* __restrict__ Bm, int ldb, long long sB,
    float* __restrict__ C, int ldc, long long sC,
    const float* __restrict__ Res, int K, int mode)
{
    const int z = blockIdx.z;
    A  += (long long)z * sA;
    Bm += (long long)z * sB;
    C  += (long long)z * sC;

    const int m0 = blockIdx.y * 128, n0 = blockIdx.x * 128;

    __shared__ __align__(16) bf16 As[128][40];
    __shared__ __align__(16) bf16 Bs[32][136];

    const int tid  = threadIdx.x;
    const int warp = tid >> 5;
    const int wm   = warp & 1;      // 0..1 -> 64 rows
    const int wn   = warp >> 1;     // 0..3 -> 32 cols

    wmma::fragment<wmma::accumulator, 16, 16, 16, float> acc[4][2];
    if (mode == 2) {
#pragma unroll
        for (int i = 0; i < 4; i++)
#pragma unroll
            for (int j = 0; j < 2; j++)
                wmma::load_matrix_sync(acc[i][j],
                    Res + (long long)(m0 + wm * 64 + i * 16) * ldc + n0 + wn * 32 + j * 16,
                    ldc, wmma::mem_row_major);
    } else {
#pragma unroll
        for (int i = 0; i < 4; i++)
#pragma unroll
            for (int j = 0; j < 2; j++)
                wmma::fill_fragment(acc[i][j], 0.f);
    }

    const int arow = tid >> 2,  acg = (tid & 3) * 8;
    const int brow = tid >> 4,  bcg = (tid & 15) * 8;

    for (int k0 = 0; k0 < K; k0 += 32) {
        uint4 a0 = *(const uint4*)(A + (long long)(m0 + arow)      * lda + k0 + acg);
        uint4 a1 = *(const uint4*)(A + (long long)(m0 + arow + 64) * lda + k0 + acg);
        uint4 b0 = *(const uint4*)(Bm + (long long)(k0 + brow)      * ldb + n0 + bcg);
        uint4 b1 = *(const uint4*)(Bm + (long long)(k0 + brow + 16) * ldb + n0 + bcg);
        __syncthreads();
        *(uint4*)&As[arow][acg]      = a0;
        *(uint4*)&As[arow + 64][acg] = a1;
        *(uint4*)&Bs[brow][bcg]      = b0;
        *(uint4*)&Bs[brow + 16][bcg] = b1;
        __syncthreads();
#pragma unroll
        for (int kk = 0; kk < 32; kk += 16) {
            wmma::fragment<wmma::matrix_a, 16, 16, 16, bf16, wmma::row_major> af[4];
            wmma::fragment<wmma::matrix_b, 16, 16, 16, bf16, wmma::row_major> bfr[2];
#pragma unroll
            for (int i = 0; i < 4; i++)
                wmma::load_matrix_sync(af[i], &As[wm * 64 + i * 16][kk], 40);
#pragma unroll
            for (int j = 0; j < 2; j++)
                wmma::load_matrix_sync(bfr[j], &Bs[kk][wn * 32 + j * 16], 136);
#pragma unroll
            for (int i = 0; i < 4; i++)
#pragma unroll
                for (int j = 0; j < 2; j++)
                    wmma::mma_sync(acc[i][j], af[i], bfr[j], acc[i][j]);
        }
    }

#pragma unroll
    for (int i = 0; i < 4; i++)
#pragma unroll
        for (int j = 0; j < 2; j++) {
            if (mode == 1) {
#pragma unroll
                for (int e = 0; e < acc[i][j].num_elements; e++)
                    acc[i][j].x[e] = fmaxf(acc[i][j].x[e], 0.f);
            }
            wmma::store_matrix_sync(
                C + (long long)(m0 + wm * 64 + i * 16) * ldc + n0 + wn * 32 + j * 16,
                acc[i][j], ldc, wmma::mem_row_major);
        }
}

// =====================================================================
// bf16 WMMA scores (layer 2, NT): S = 0.125 * Q @ K^T, per (b,h)
// =====================================================================
__global__ void __launch_bounds__(256) bscores(
    const bf16* __restrict__ Q, const bf16* __restrict__ Kv, float* __restrict__ S)
{
    const int z = blockIdx.z;
    const int b = z >> 3, h = z & 7;
    const bf16* Ab = Q  + ((long long)b * TT) * DD + h * DHH;
    const bf16* Bb = Kv + ((long long)b * TT) * DD + h * DHH;
    float* Cb = S + (long long)z * TT * TT;

    const int m0 = blockIdx.y * 128, n0 = blockIdx.x * 128;

    __shared__ __align__(16) bf16 As[128][40];
    __shared__ __align__(16) bf16 Ks[128][40];

    const int tid  = threadIdx.x;
    const int warp = tid >> 5;
    const int wm   = warp & 1;
    const int wn   = warp >> 1;

    wmma::fragment<wmma::accumulator, 16, 16, 16, float> acc[4][2];
#pragma unroll
    for (int i = 0; i < 4; i++)
#pragma unroll
        for (int j = 0; j < 2; j++)
            wmma::fill_fragment(acc[i][j], 0.f);

    const int arow = tid >> 2, acg = (tid & 3) * 8;

#pragma unroll
    for (int k0 = 0; k0 < DHH; k0 += 32) {
        uint4 a0 = *(const uint4*)(Ab + (long long)(m0 + arow)      * DD + k0 + acg);
        uint4 a1 = *(const uint4*)(Ab + (long long)(m0 + arow + 64) * DD + k0 + acg);
        uint4 b0 = *(const uint4*)(Bb + (long long)(n0 + arow)      * DD + k0 + acg);
        uint4 b1 = *(const uint4*)(Bb + (long long)(n0 + arow + 64) * DD + k0 + acg);
        __syncthreads();
        *(uint4*)&As[arow][acg]      = a0;
        *(uint4*)&As[arow + 64][acg] = a1;
        *(uint4*)&Ks[arow][acg]      = b0;
        *(uint4*)&Ks[arow + 64][acg] = b1;
        __syncthreads();
#pragma unroll
        for (int kk = 0; kk < 32; kk += 16) {
            wmma::fragment<wmma::matrix_a, 16, 16, 16, bf16, wmma::row_major> af[4];
            wmma::fragment<wmma::matrix_b, 16, 16, 16, bf16, wmma::col_major> bfr[2];
#pragma unroll
            for (int i = 0; i < 4; i++)
                wmma::load_matrix_sync(af[i], &As[wm * 64 + i * 16][kk], 40);
#pragma unroll
            for (int j = 0; j < 2; j++)
                wmma::load_matrix_sync(bfr[j], &Ks[wn * 32 + j * 16][kk], 40);
#pragma unroll
            for (int i = 0; i < 4; i++)
#pragma unroll
                for (int j = 0; j < 2; j++)
                    wmma::mma_sync(acc[i][j], af[i], bfr[j], acc[i][j]);
        }
    }

#pragma unroll
    for (int i = 0; i < 4; i++)
#pragma unroll
        for (int j = 0; j < 2; j++) {
#pragma unroll
            for (int e = 0; e < acc[i][j].num_elements; e++)
                acc[i][j].x[e] *= 0.125f;
            wmma::store_matrix_sync(
                Cb + (long long)(m0 + wm * 64 + i * 16) * TT + n0 + wn * 32 + j * 16,
                acc[i][j], TT, wmma::mem_row_major);
        }
}

// =====================================================================
// bf16 WMMA PV: ctx[b,q,h*64+n] = P @ V.  128x64x32 tile, 8 warps
// (4 along M x 2 along N), warp tile 32x32.
// =====================================================================
__global__ void __launch_bounds__(256) bpv(
    const bf16* __restrict__ P, const bf16* __restrict__ V, float* __restrict__ ctx)
{
    const int z = blockIdx.y;
    const int b = z >> 3, h = z & 7;
    const bf16* Ab = P + (long long)z * TT * TT;
    const bf16* Bb = V + ((long long)b * TT) * DD + h * DHH;
    float* Cb = ctx + ((long long)b * TT) * DD + h * DHH;

    const int m0 = blockIdx.x * 128;

    __shared__ __align__(16) bf16 As[128][40];
    __shared__ __align__(16) bf16 Bs[32][72];

    const int tid  = threadIdx.x;
    const int warp = tid >> 5;
    const int wm   = warp & 3;      // 0..3 -> 32 rows
    const int wn   = warp >> 2;     // 0..1 -> 32 cols

    wmma::fragment<wmma::accumulator, 16, 16, 16, float> acc[2][2];
#pragma unroll
    for (int i = 0; i < 2; i++)
#pragma unroll
        for (int j = 0; j < 2; j++)
            wmma::fill_fragment(acc[i][j], 0.f);

    const int arow = tid >> 2, acg = (tid & 3) * 8;
    const int brow = tid >> 3, bcg = (tid & 7) * 8;

    for (int k0 = 0; k0 < TT; k0 += 32) {
        uint4 a0 = *(const uint4*)(Ab + (long long)(m0 + arow)      * TT + k0 + acg);
        uint4 a1 = *(const uint4*)(Ab + (long long)(m0 + arow + 64) * TT + k0 + acg);
        uint4 b0 = *(const uint4*)(Bb + (long long)(k0 + brow) * DD + bcg);
        __syncthreads();
        *(uint4*)&As[arow][acg]      = a0;
        *(uint4*)&As[arow + 64][acg] = a1;
        *(uint4*)&Bs[brow][bcg]      = b0;
        __syncthreads();
#pragma unroll
        for (int kk = 0; kk < 32; kk += 16) {
            wmma::fragment<wmma::matrix_a, 16, 16, 16, bf16, wmma::row_major> af[2];
            wmma::fragment<wmma::matrix_b, 16, 16, 16, bf16, wmma::row_major> bfr[2];
#pragma unroll
            for (int i = 0; i < 2; i++)
                wmma::load_matrix_sync(af[i], &As[wm * 32 + i * 16][kk], 40);
#pragma unroll
            for (int j = 0; j < 2; j++)
                wmma::load_matrix_sync(bfr[j], &Bs[kk][wn * 32 + j * 16], 72);
#pragma unroll
            for (int i = 0; i < 2; i++)
#pragma unroll
                for (int j = 0; j < 2; j++)
                    wmma::mma_sync(acc[i][j], af[i], bfr[j], acc[i][j]);
        }
    }

#pragma unroll
    for (int i = 0; i < 2; i++)
#pragma unroll
        for (int j = 0; j < 2; j++)
            wmma::store_matrix_sync(
                Cb + (long long)(m0 + wm * 32 + i * 16) * DD + wn * 32 + j * 16,
                acc[i][j], DD, wmma::mem_row_major);
}

// =====================================================================
// Row softmax over T=1024 (in place, fp32) + bf16 copy of probs.
// ids != null => block-diagonal window mask.
// =====================================================================
__global__ void __launch_bounds__(256) softmax_rows_k(float* __restrict__ S,
                                                      const int* __restrict__ ids,
                                                      bf16* __restrict__ Pbf)
{
    const long long r = blockIdx.x;
    const int q  = (int)(r & (TT - 1));
    const int bh = (int)(r >> 10);
    const int b  = bh >> 3;
    float* row = S + r * TT;
    bf16*  rbf = Pbf + r * TT;
    const int tid = threadIdx.x;

    __shared__ float sh[256];

    const float NEG = __int_as_float(0xff800000);
    const int idbase = b * TT;
    const int qid = ids ? ids[idbase + q] : 0;

    float v[4];
    float mx = -3.4e38f;
#pragma unroll
    for (int i = 0; i < 4; i++) {
        int k = tid + i * 256;
        float x = row[k];
        if (ids && ids[idbase + k] != qid) x = NEG;
        v[i] = x;
        mx = fmaxf(mx, x);
    }
    sh[tid] = mx; __syncthreads();
    for (int s = 128; s > 0; s >>= 1) { if (tid < s) sh[tid] = fmaxf(sh[tid], sh[tid + s]); __syncthreads(); }
    mx = sh[0]; __syncthreads();

    float e[4];
    float sum = 0.f;
#pragma unroll
    for (int i = 0; i < 4; i++) { e[i] = expf(v[i] - mx); sum += e[i]; }
    sh[tid] = sum; __syncthreads();
    for (int s = 128; s > 0; s >>= 1) { if (tid < s) sh[tid] += sh[tid + s]; __syncthreads(); }
    const float inv = 1.f / sh[0];

#pragma unroll
    for (int i = 0; i < 4; i++) {
        float p = e[i] * inv;
        row[tid + i * 256] = p;
        rbf[tid + i * 256] = __float2bfloat16(p);
    }
}

// column sum (double accum): w[b,k] = (1/H) sum_{h,q} P[b,h,q,k]
__global__ void __launch_bounds__(256) colsum_k(const float* __restrict__ P,
                                                float* __restrict__ w)
{
    const int b = blockIdx.x;
    const int k = blockIdx.y * 256 + threadIdx.x;
    const float* p = P + (long long)b * HH * TT * TT + k;
    double s0 = 0, s1 = 0, s2 = 0, s3 = 0;
    for (long long i = 0; i < (long long)HH * TT; i += 4) {
        s0 += (double)p[i * TT];
        s1 += (double)p[(i + 1) * TT];
        s2 += (double)p[(i + 2) * TT];
        s3 += (double)p[(i + 3) * TT];
    }
    w[b * TT + k] = (float)(((s0 + s1) + (s2 + s3)) * (1.0 / HH));
}

__global__ void __launch_bounds__(256) minmax_k(const float* __restrict__ w,
                                                float* __restrict__ mm)
{
    const int b = blockIdx.x, tid = threadIdx.x;
    __shared__ float smn[256], smx[256];
    float mn = 3.4e38f, mx = -3.4e38f;
    for (int t = tid; t < TT; t += 256) {
        float x = w[b * TT + t];
        mn = fminf(mn, x); mx = fmaxf(mx, x);
    }
    smn[tid] = mn; smx[tid] = mx; __syncthreads();
    for (int s = 128; s > 0; s >>= 1) {
        if (tid < s) { smn[tid] = fminf(smn[tid], smn[tid + s]); smx[tid] = fmaxf(smx[tid], smx[tid + s]); }
        __syncthreads();
    }
    if (tid == 0) { mm[b * 2] = smn[0]; mm[b * 2 + 1] = smx[0]; }
}

__global__ void winscan_k(const float* __restrict__ w, const float* __restrict__ mm,
                          int* __restrict__ ids)
{
    const int b = threadIdx.x;
    if (b >= BB) return;
    const float mn  = mm[b * 2];
    const float den = mm[b * 2 + 1] - mn + 1e-8f;
    const float* wb = w + b * TT;
    int* idb = ids + b * TT;

    bool cur = ((wb[0] - mn) / den) >= 0.5f;
    int start = 0, wid = 0;
    idb[0] = 0;
    for (int t = 1; t < TT; t++) {
        bool wt = ((wb[t] - mn) / den) >= 0.5f;
        if (wt != cur) {
            cur = wt;
            if (start + 1 != t) { start = t; wid++; }
        }
        idb[t] = wid;
    }
}

__global__ void __launch_bounds__(256) softmax1d_k(const float* __restrict__ w,
                                                   float* __restrict__ wl)
{
    const int b = blockIdx.x, tid = threadIdx.x;
    __shared__ float sh[256];
    float v[4];
    float mx = -3.4e38f;
#pragma unroll
    for (int i = 0; i < 4; i++) { v[i] = w[b * TT + tid + i * 256]; mx = fmaxf(mx, v[i]); }
    sh[tid] = mx; __syncthreads();
    for (int s = 128; s > 0; s >>= 1) { if (tid < s) sh[tid] = fmaxf(sh[tid], sh[tid + s]); __syncthreads(); }
    mx = sh[0]; __syncthreads();
    float e[4], sum = 0.f;
#pragma unroll
    for (int i = 0; i < 4; i++) { e[i] = expf(v[i] - mx); sum += e[i]; }
    sh[tid] = sum; __syncthreads();
    for (int s = 128; s > 0; s >>= 1) { if (tid < s) sh[tid] += sh[tid + s]; __syncthreads(); }
    const float inv = 1.f / sh[0];
#pragma unroll
    for (int i = 0; i < 4; i++) wl[b * TT + tid + i * 256] = e[i] * inv;
}

// in-place LayerNorm over D=512 + optional bf16 dual write
__global__ void __launch_bounds__(256) ln_k(float* __restrict__ X, bf16* __restrict__ Xbf)
{
    const long long r = blockIdx.x;
    float* row = X + r * DD;
    const int tid = threadIdx.x;
    __shared__ float sh[256];

    float x0 = row[tid], x1 = row[tid + 256];
    sh[tid] = x0 + x1; __syncthreads();
    for (int s = 128; s > 0; s >>= 1) { if (tid < s) sh[tid] += sh[tid + s]; __syncthreads(); }
    const float mean = sh[0] * (1.f / DD);
    __syncthreads();

    const float d0 = x0 - mean, d1 = x1 - mean;
    sh[tid] = d0 * d0 + d1 * d1; __syncthreads();
    for (int s = 128; s > 0; s >>= 1) { if (tid < s) sh[tid] += sh[tid + s]; __syncthreads(); }
    const float var = sh[0] * (1.f / DD);
    const float rs = 1.f / sqrtf(var + 1e-5f);
    const float y0 = d0 * rs, y1 = d1 * rs;
    row[tid] = y0;
    row[tid + 256] = y1;
    if (Xbf) {
        Xbf[r * DD + tid]       = __float2bfloat16(y0);
        Xbf[r * DD + tid + 256] = __float2bfloat16(y1);
    }
}

// float -> bf16 conversion, 4 elems/thread (n % 1024 == 0)
__global__ void __launch_bounds__(256) f2bf_k(const float* __restrict__ src,
                                              bf16* __restrict__ dst, long long n)
{
    const long long i = ((long long)blockIdx.x * 256 + threadIdx.x) * 4;
    if (i >= n) return;
    float4 v = *(const float4*)(src + i);
    __nv_bfloat162 p0, p1;
    p0.x = __float2bfloat16(v.x); p0.y = __float2bfloat16(v.y);
    p1.x = __float2bfloat16(v.z); p1.y = __float2bfloat16(v.w);
    *(__nv_bfloat162*)(dst + i)     = p0;
    *(__nv_bfloat162*)(dst + i + 2) = p1;
}

// out[:, 0:T, :] = 0 ; out[:, T:2T, :] = x
__global__ void __launch_bounds__(256) outinit_k(const float* __restrict__ x,
                                                 float* __restrict__ out)
{
    const long long idx = (long long)blockIdx.x * 256 + threadIdx.x;
    const int d = (int)(idx & (DD - 1));
    const long long rb = idx >> 9;
    const int r = (int)(rb & (2 * TT - 1));
    const int b = (int)(rb >> 11);
    out[idx] = (r < TT) ? 0.f : x[((long long)b * TT + (r - TT)) * DD + d];
}

// segmented pooling
__global__ void __launch_bounds__(512) pool_k(const float* __restrict__ outl,
                                              const float* __restrict__ wl,
                                              const int* __restrict__ ids,
                                              float* __restrict__ out)
{
    const int b = blockIdx.x, d = threadIdx.x;
    __shared__ int   sids[TT];
    __shared__ float swl[TT];
    for (int t = d; t < TT; t += 512) {
        sids[t] = ids[b * TT + t];
        swl[t]  = wl[b * TT + t];
    }
    __syncthreads();

    const float* xb = outl + (long long)b * TT * DD + d;
    float acc = 0.f;
    for (int t0 = 0; t0 < TT; t0 += 16) {
        float vals[16];
#pragma unroll
        for (int u = 0; u < 16; u++) vals[u] = xb[(long long)(t0 + u) * DD];
#pragma unroll
        for (int u = 0; u < 16; u++) {
            const int t = t0 + u;
            acc = fmaf(vals[u], swl[t], acc);
            const int curid = sids[t];
            const bool flush = (t == TT - 1) || (sids[t + 1] != curid);
            if (flush) {
                out[((long long)b * 2 * TT + curid) * DD + d] = acc;
                acc = 0.f;
            }
        }
    }
}

__global__ void __launch_bounds__(256) mapping_k(const int* __restrict__ ids,
                                                 float* __restrict__ out2)
{
    const long long idx = (long long)blockIdx.x * 256 + threadIdx.x;
    const int j = (int)(idx & (TT - 1));
    const long long wb = idx >> 10;
    const int wrow = (int)(wb & (TT - 1));
    const int b = (int)(wb >> 10);
    out2[idx] = (ids[b * TT + j] == wrow) ? 1.f : 0.f;
}

// =====================================================================
// host
// =====================================================================
extern "C" void kernel_launch(void* const* d_in, const int* in_sizes, int n_in,
                              void* d_out, int out_size)
{
    (void)in_sizes; (void)n_in; (void)out_size;
    const float* x       = (const float*)d_in[0];
    const float* v_qkv_w = (const float*)d_in[1];
    const float* v_out_w = (const float*)d_in[2];
    const float* v_w1    = (const float*)d_in[3];
    const float* v_w2    = (const float*)d_in[4];
    const float* l_qkv_w = (const float*)d_in[5];
    const float* l_out_w = (const float*)d_in[6];
    const float* l_w1    = (const float*)d_in[7];
    const float* l_w2    = (const float*)d_in[8];
    float* out = (float*)d_out;

    float *qkv, *scores, *ctx, *tmp, *ff, *outv, *outl, *w, *mm, *wl;
    int* ids;
    bf16 *wbf, *xbf, *qkvbf, *probsbf, *ctxbf, *tmpbf, *outvbf, *ffbf;
    cudaGetSymbolAddress((void**)&qkv,    g_qkv);
    cudaGetSymbolAddress((void**)&scores, g_scores);
    cudaGetSymbolAddress((void**)&ctx,    g_ctx);
    cudaGetSymbolAddress((void**)&tmp,    g_tmp);
    cudaGetSymbolAddress((void**)&ff,     g_ff);
    cudaGetSymbolAddress((void**)&outv,   g_outv);
    cudaGetSymbolAddress((void**)&outl,   g_outl);
    cudaGetSymbolAddress((void**)&w,      g_w);
    cudaGetSymbolAddress((void**)&mm,     g_mm);
    cudaGetSymbolAddress((void**)&ids,    g_ids);
    cudaGetSymbolAddress((void**)&wl,     g_wl);
    cudaGetSymbolAddress((void**)&wbf,    g_wbf);
    cudaGetSymbolAddress((void**)&xbf,    g_xbf);
    cudaGetSymbolAddress((void**)&qkvbf,  g_qkvbf);
    cudaGetSymbolAddress((void**)&probsbf,g_probsbf);
    cudaGetSymbolAddress((void**)&ctxbf,  g_ctxbf);
    cudaGetSymbolAddress((void**)&tmpbf,  g_tmpbf);
    cudaGetSymbolAddress((void**)&outvbf, g_outvbf);
    cudaGetSymbolAddress((void**)&ffbf,   g_ffbf);

    const dim3 blk(256);
    const long long sQKVw = (long long)DD * DD;
    const long long sQKVc = (long long)BT * DD;

    // ---- weight + input conversions ----
    auto cvt = [&](const float* s, bf16* d, long long n) {
        f2bf_k<<<(unsigned)((n + 1023) / 1024), blk>>>(s, d, n);
    };
    cvt(v_qkv_w, wbf + OFF_VQKV, 3LL * DD * DD);
    cvt(v_out_w, wbf + OFF_VOUT, (long long)DD * DD);
    cvt(v_w1,    wbf + OFF_VW1,  (long long)DD * FFD);
    cvt(v_w2,    wbf + OFF_VW2,  (long long)FFD * DD);
    cvt(l_qkv_w, wbf + OFF_LQKV, 3LL * DD * DD);
    cvt(l_out_w, wbf + OFF_LOUT, (long long)DD * DD);
    cvt(l_w1,    wbf + OFF_LW1,  (long long)DD * FFD);
    cvt(l_w2,    wbf + OFF_LW2,  (long long)FFD * DD);
    cvt(x, xbf, sQKVc);

    // ---------------- layer 1 (vanilla) ----------------
    // Q,K in fp32 (threshold-critical)
    sgemm64<<<dim3(DD / 64, BT / 64, 2), blk>>>(x, DD, 0, v_qkv_w, DD, sQKVw,
                                                qkv, DD, sQKVc, DD);
    // V in bf16
    bgemm_nn<<<dim3(DD / 128, BT / 128, 1), blk>>>(xbf, DD, 0,
                                                   wbf + OFF_VQKV + 2 * sQKVw, DD, 0,
                                                   qkv + 2 * sQKVc, DD, 0, nullptr, DD, 0);
    attn_scores_k<<<dim3(TT / 64, TT / 64, BHH), blk>>>(qkv, qkv + sQKVc, scores);
    softmax_rows_k<<<BHH * TT, blk>>>(scores, nullptr, probsbf);
    colsum_k<<<dim3(BB, TT / 256), blk>>>(scores, w);
    minmax_k<<<BB, blk>>>(w, mm);
    winscan_k<<<1, 32>>>(w, mm, ids);
    cvt(qkv + 2 * sQKVc, qkvbf + 2 * sQKVc, sQKVc);
    bpv<<<dim3(TT / 128, BHH), blk>>>(probsbf, qkvbf + 2 * sQKVc, ctx);
    cvt(ctx, ctxbf, sQKVc);
    bgemm_nn<<<dim3(DD / 128, BT / 128, 1), blk>>>(ctxbf, DD, 0, wbf + OFF_VOUT, DD, 0,
                                                   tmp, DD, 0, x, DD, 2);
    ln_k<<<BT, blk>>>(tmp, tmpbf);
    bgemm_nn<<<dim3(FFD / 128, BT / 128, 1), blk>>>(tmpbf, DD, 0, wbf + OFF_VW1, FFD, 0,
                                                    ff, FFD, 0, nullptr, DD, 1);
    cvt(ff, ffbf, (long long)BT * FFD);
    bgemm_nn<<<dim3(DD / 128, BT / 128, 1), blk>>>(ffbf, FFD, 0, wbf + OFF_VW2, DD, 0,
                                                   outv, DD, 0, tmp, FFD, 2);
    ln_k<<<BT, blk>>>(outv, outvbf);

    // ---------------- layer 2 (windowed, all bf16) ----------------
    bgemm_nn<<<dim3(DD / 128, BT / 128, 3), blk>>>(outvbf, DD, 0, wbf + OFF_LQKV, DD, sQKVw,
                                                   qkv, DD, sQKVc, nullptr, DD, 0);
    cvt(qkv, qkvbf, 3 * sQKVc);
    bscores<<<dim3(TT / 128, TT / 128, BHH), blk>>>(qkvbf, qkvbf + sQKVc, scores);
    softmax_rows_k<<<BHH * TT, blk>>>(scores, ids, probsbf);
    colsum_k<<<dim3(BB, TT / 256), blk>>>(scores, w);
    softmax1d_k<<<BB, blk>>>(w, wl);
    bpv<<<dim3(TT / 128, BHH), blk>>>(probsbf, qkvbf + 2 * sQKVc, ctx);
    cvt(ctx, ctxbf, sQKVc);
    bgemm_nn<<<dim3(DD / 128, BT / 128, 1), blk>>>(ctxbf, DD, 0, wbf + OFF_LOUT, DD, 0,
                                                   tmp, DD, 0, outv, DD, 2);
    ln_k<<<BT, blk>>>(tmp, tmpbf);
    bgemm_nn<<<dim3(FFD / 128, BT / 128, 1), blk>>>(tmpbf, DD, 0, wbf + OFF_LW1, FFD, 0,
                                                    ff, FFD, 0, nullptr, DD, 1);
    cvt(ff, ffbf, (long long)BT * FFD);
    bgemm_nn<<<dim3(DD / 128, BT / 128, 1), blk>>>(ffbf, FFD, 0, wbf + OFF_LW2, DD, 0,
                                                   outl, DD, 0, tmp, FFD, 2);
    ln_k<<<BT, blk>>>(outl, nullptr);

    // ---------------- outputs ----------------
    const long long n1 = (long long)BB * 2 * TT * DD;
    outinit_k<<<(unsigned)(n1 / 256), blk>>>(x, out);
    pool_k<<<BB, 512>>>(outl, wl, ids, out);
    mapping_k<<<(unsigned)(((long long)BB * TT * TT) / 256), blk>>>(ids, out + n1);
}

// round 14
// speedup vs baseline: 1.5938x; 1.0019x over previous
#include <cuda_runtime.h>
#include <cuda_bf16.h>
#include <mma.h>
#include <math.h>

using namespace nvcuda;
typedef __nv_bfloat16 bf16;

// ---------------- problem constants ----------------
#define BB   8
#define HH   8
#define TT   1024
#define DD   512
#define DHH  64
#define FFD  2048
#define BT   8192        // B*T
#define BHH  64          // B*H

// weight offsets in the packed bf16 weight buffer
#define OFF_VQKV 0LL
#define OFF_VOUT (3LL*DD*DD)
#define OFF_VW1  (OFF_VOUT + (long long)DD*DD)
#define OFF_VW2  (OFF_VW1 + (long long)DD*FFD)
#define OFF_LQKV (OFF_VW2 + (long long)FFD*DD)
#define OFF_LOUT (OFF_LQKV + 3LL*DD*DD)
#define OFF_LW1  (OFF_LOUT + (long long)DD*DD)
#define OFF_LW2  (OFF_LW1 + (long long)DD*FFD)
#define WBF_TOTAL (OFF_LW2 + (long long)FFD*DD)

// ---------------- device scratch (no allocs allowed) ----------------
__device__ float g_qkv[3ll * BT * DD];                 // 48 MB
__device__ float g_scores[(long long)BHH * TT * TT];   // 256 MB (scores -> probs in place)
__device__ float g_ctx[(long long)BT * DD];
__device__ float g_tmp[(long long)BT * DD];
__device__ float g_ff[(long long)BT * FFD];
__device__ float g_outv[(long long)BT * DD];
__device__ float g_outl[(long long)BT * DD];
__device__ float g_w[BB * TT];
__device__ float g_mm[BB * 2];
__device__ int   g_ids[BB * TT];
__device__ float g_wl[BB * TT];

__device__ bf16 g_wbf[WBF_TOTAL];                      // 12 MB packed weights
__device__ bf16 g_xbf[(long long)BT * DD];
__device__ bf16 g_qkvbf[3ll * BT * DD];
__device__ bf16 g_probsbf[(long long)BHH * TT * TT];   // 128 MB
__device__ bf16 g_ctxbf[(long long)BT * DD];
__device__ bf16 g_tmpbf[(long long)BT * DD];
__device__ bf16 g_outvbf[(long long)BT * DD];
__device__ bf16 g_ffbf[(long long)BT * FFD];

// =====================================================================
// fp32 SGEMM (64x64 tile) — used ONLY for the threshold-critical layer-1
// Q,K projections. mode 0 store.
// =====================================================================
__global__ void __launch_bounds__(256) sgemm64(
    const float* __restrict__ A, int lda, long long sA,
    const float* __restrict__ Bm, int ldb, long long sB,
    float* __restrict__ C, int ldc, long long sC,
    int K)
{
    int z = blockIdx.z;
    A  += (long long)z * sA;
    Bm += (long long)z * sB;
    C  += (long long)z * sC;

    const int m0 = blockIdx.y * 64, n0 = blockIdx.x * 64;

    __shared__ __align__(16) float As[16][68];
    __shared__ __align__(16) float Bs[16][68];

    const int tid  = threadIdx.x;
    const int tr   = (tid >> 4) << 2;
    const int tc   = (tid & 15) << 2;
    const int la_r = tid >> 2;
    const int la_c = (tid & 3) << 2;
    const int lb_r = tid >> 4;
    const int lb_c = (tid & 15) << 2;

    float acc[4][4];
#pragma unroll
    for (int i = 0; i < 4; i++)
#pragma unroll
        for (int j = 0; j < 4; j++) acc[i][j] = 0.f;

    const float* Aptr = A + (long long)(m0 + la_r) * lda + la_c;
    const float* Bptr = Bm + (long long)lb_r * ldb + n0 + lb_c;

    for (int k0 = 0; k0 < K; k0 += 16) {
        float4 a4 = *(const float4*)(Aptr + k0);
        float4 b4 = *(const float4*)(Bptr + (long long)k0 * ldb);
        __syncthreads();
        As[la_c + 0][la_r] = a4.x;
        As[la_c + 1][la_r] = a4.y;
        As[la_c + 2][la_r] = a4.z;
        As[la_c + 3][la_r] = a4.w;
        *(float4*)&Bs[lb_r][lb_c] = b4;
        __syncthreads();
#pragma unroll
        for (int kk = 0; kk < 16; kk++) {
            float4 av = *(const float4*)&As[kk][tr];
            float4 bv = *(const float4*)&Bs[kk][tc];
            float a[4] = {av.x, av.y, av.z, av.w};
            float b[4] = {bv.x, bv.y, bv.z, bv.w};
#pragma unroll
            for (int i = 0; i < 4; i++)
#pragma unroll
                for (int j = 0; j < 4; j++)
                    acc[i][j] = fmaf(a[i], b[j], acc[i][j]);
        }
    }

#pragma unroll
    for (int i = 0; i < 4; i++) {
        long long rowoff = (long long)(m0 + tr + i) * ldc + n0 + tc;
#pragma unroll
        for (int j = 0; j < 4; j++)
            C[rowoff + j] = acc[i][j];
    }
}

// =====================================================================
// fp32 attention scores (layer 1, threshold-critical):
// S[b,h,q,k] = (1/8) sum_d Q*K
// =====================================================================
__global__ void __launch_bounds__(256) attn_scores_k(
    const float* __restrict__ Q, const float* __restrict__ Km, float* __restrict__ S)
{
    const int z = blockIdx.z;
    const int b = z >> 3, h = z & 7;
    const float* Ab = Q  + ((long long)b * TT) * DD + h * DHH;
    const float* Bb = Km + ((long long)b * TT) * DD + h * DHH;
    float* Cb = S + (long long)z * TT * TT;

    const int m0 = blockIdx.y * 64, n0 = blockIdx.x * 64;

    __shared__ __align__(16) float As[16][68];
    __shared__ __align__(16) float Bs[16][68];

    const int tid = threadIdx.x;
    const int tr  = (tid >> 4) << 2;
    const int tc  = (tid & 15) << 2;
    const int l_r = tid >> 2;
    const int l_c = (tid & 3) << 2;

    float acc[4][4];
#pragma unroll
    for (int i = 0; i < 4; i++)
#pragma unroll
        for (int j = 0; j < 4; j++) acc[i][j] = 0.f;

    const float* Ap = Ab + (long long)(m0 + l_r) * DD + l_c;
    const float* Bp = Bb + (long long)(n0 + l_r) * DD + l_c;

#pragma unroll
    for (int k0 = 0; k0 < DHH; k0 += 16) {
        float4 a4 = *(const float4*)(Ap + k0);
        float4 b4 = *(const float4*)(Bp + k0);
        __syncthreads();
        As[l_c + 0][l_r] = a4.x; As[l_c + 1][l_r] = a4.y;
        As[l_c + 2][l_r] = a4.z; As[l_c + 3][l_r] = a4.w;
        Bs[l_c + 0][l_r] = b4.x; Bs[l_c + 1][l_r] = b4.y;
        Bs[l_c + 2][l_r] = b4.z; Bs[l_c + 3][l_r] = b4.w;
        __syncthreads();
#pragma unroll
        for (int kk = 0; kk < 16; kk++) {
            float4 av = *(const float4*)&As[kk][tr];
            float4 bv = *(const float4*)&Bs[kk][tc];
            float a[4] = {av.x, av.y, av.z, av.w};
            float b[4] = {bv.x, bv.y, bv.z, bv.w};
#pragma unroll
            for (int i = 0; i < 4; i++)
#pragma unroll
                for (int j = 0; j < 4; j++)
                    acc[i][j] = fmaf(a[i], b[j], acc[i][j]);
        }
    }

#pragma unroll
    for (int i = 0; i < 4; i++) {
        long long rowoff = (long long)(m0 + tr + i) * TT + n0 + tc;
#pragma unroll
        for (int j = 0; j < 4; j++)
            Cb[rowoff + j] = acc[i][j] * 0.125f;
    }
}

// =====================================================================
// bf16 WMMA GEMM (NN): C[M,N] = A@B (+Res / relu). 128x128x32 tile,
// 8 warps (2 along M x 4 along N), warp tile 64x32.
// mode: 0 store, 1 relu, 2 += Res
// =====================================================================
__global__ void __launch_bounds__(256) bgemm_nn(
    const bf16* __restrict__ A, int lda, long long sA,
    const bf16* __restrict__ Bm, int ldb, long long sB,
    float* __restrict__ C, int ldc, long long sC,
    const float* __restrict__ Res, int K, int mode)
{
    const int z = blockIdx.z;
    A  += (long long)z * sA;
    Bm += (long long)z * sB;
    C  += (long long)z * sC;

    const int m0 = blockIdx.y * 128, n0 = blockIdx.x * 128;

    __shared__ __align__(16) bf16 As[128][40];
    __shared__ __align__(16) bf16 Bs[32][136];

    const int tid  = threadIdx.x;
    const int warp = tid >> 5;
    const int wm   = warp & 1;      // 0..1 -> 64 rows
    const int wn   = warp >> 1;     // 0..3 -> 32 cols

    wmma::fragment<wmma::accumulator, 16, 16, 16, float> acc[4][2];
    if (mode == 2) {
#pragma unroll
        for (int i = 0; i < 4; i++)
#pragma unroll
            for (int j = 0; j < 2; j++)
                wmma::load_matrix_sync(acc[i][j],
                    Res + (long long)(m0 + wm * 64 + i * 16) * ldc + n0 + wn * 32 + j * 16,
                    ldc, wmma::mem_row_major);
    } else {
#pragma unroll
        for (int i = 0; i < 4; i++)
#pragma unroll
            for (int j = 0; j < 2; j++)
                wmma::fill_fragment(acc[i][j], 0.f);
    }

    const int arow = tid >> 2,  acg = (tid & 3) * 8;
    const int brow = tid >> 4,  bcg = (tid & 15) * 8;

    for (int k0 = 0; k0 < K; k0 += 32) {
        uint4 a0 = *(const uint4*)(A + (long long)(m0 + arow)      * lda + k0 + acg);
        uint4 a1 = *(const uint4*)(A + (long long)(m0 + arow + 64) * lda + k0 + acg);
        uint4 b0 = *(const uint4*)(Bm + (long long)(k0 + brow)      * ldb + n0 + bcg);
        uint4 b1 = *(const uint4*)(Bm + (long long)(k0 + brow + 16) * ldb + n0 + bcg);
        __syncthreads();
        *(uint4*)&As[arow][acg]      = a0;
        *(uint4*)&As[arow + 64][acg] = a1;
        *(uint4*)&Bs[brow][bcg]      = b0;
        *(uint4*)&Bs[brow + 16][bcg] = b1;
        __syncthreads();
#pragma unroll
        for (int kk = 0; kk < 32; kk += 16) {
            wmma::fragment<wmma::matrix_a, 16, 16, 16, bf16, wmma::row_major> af[4];
            wmma::fragment<wmma::matrix_b, 16, 16, 16, bf16, wmma::row_major> bfr[2];
#pragma unroll
            for (int i = 0; i < 4; i++)
                wmma::load_matrix_sync(af[i], &As[wm * 64 + i * 16][kk], 40);
#pragma unroll
            for (int j = 0; j < 2; j++)
                wmma::load_matrix_sync(bfr[j], &Bs[kk][wn * 32 + j * 16], 136);
#pragma unroll
            for (int i = 0; i < 4; i++)
#pragma unroll
                for (int j = 0; j < 2; j++)
                    wmma::mma_sync(acc[i][j], af[i], bfr[j], acc[i][j]);
        }
    }

#pragma unroll
    for (int i = 0; i < 4; i++)
#pragma unroll
        for (int j = 0; j < 2; j++) {
            if (mode == 1) {
#pragma unroll
                for (int e = 0; e < acc[i][j].num_elements; e++)
                    acc[i][j].x[e] = fmaxf(acc[i][j].x[e], 0.f);
            }
            wmma::store_matrix_sync(
                C + (long long)(m0 + wm * 64 + i * 16) * ldc + n0 + wn * 32 + j * 16,
                acc[i][j], ldc, wmma::mem_row_major);
        }
}

// =====================================================================
// bf16 WMMA scores (layer 2, NT): S = 0.125 * Q @ K^T, per (b,h)
// =====================================================================
__global__ void __launch_bounds__(256) bscores(
    const bf16* __restrict__ Q, const bf16* __restrict__ Kv, float* __restrict__ S)
{
    const int z = blockIdx.z;
    const int b = z >> 3, h = z & 7;
    const bf16* Ab = Q  + ((long long)b * TT) * DD + h * DHH;
    const bf16* Bb = Kv + ((long long)b * TT) * DD + h * DHH;
    float* Cb = S + (long long)z * TT * TT;

    const int m0 = blockIdx.y * 128, n0 = blockIdx.x * 128;

    __shared__ __align__(16) bf16 As[128][40];
    __shared__ __align__(16) bf16 Ks[128][40];

    const int tid  = threadIdx.x;
    const int warp = tid >> 5;
    const int wm   = warp & 1;
    const int wn   = warp >> 1;

    wmma::fragment<wmma::accumulator, 16, 16, 16, float> acc[4][2];
#pragma unroll
    for (int i = 0; i < 4; i++)
#pragma unroll
        for (int j = 0; j < 2; j++)
            wmma::fill_fragment(acc[i][j], 0.f);

    const int arow = tid >> 2, acg = (tid & 3) * 8;

#pragma unroll
    for (int k0 = 0; k0 < DHH; k0 += 32) {
        uint4 a0 = *(const uint4*)(Ab + (long long)(m0 + arow)      * DD + k0 + acg);
        uint4 a1 = *(const uint4*)(Ab + (long long)(m0 + arow + 64) * DD + k0 + acg);
        uint4 b0 = *(const uint4*)(Bb + (long long)(n0 + arow)      * DD + k0 + acg);
        uint4 b1 = *(const uint4*)(Bb + (long long)(n0 + arow + 64) * DD + k0 + acg);
        __syncthreads();
        *(uint4*)&As[arow][acg]      = a0;
        *(uint4*)&As[arow + 64][acg] = a1;
        *(uint4*)&Ks[arow][acg]      = b0;
        *(uint4*)&Ks[arow + 64][acg] = b1;
        __syncthreads();
#pragma unroll
        for (int kk = 0; kk < 32; kk += 16) {
            wmma::fragment<wmma::matrix_a, 16, 16, 16, bf16, wmma::row_major> af[4];
            wmma::fragment<wmma::matrix_b, 16, 16, 16, bf16, wmma::col_major> bfr[2];
#pragma unroll
            for (int i = 0; i < 4; i++)
                wmma::load_matrix_sync(af[i], &As[wm * 64 + i * 16][kk], 40);
#pragma unroll
            for (int j = 0; j < 2; j++)
                wmma::load_matrix_sync(bfr[j], &Ks[wn * 32 + j * 16][kk], 40);
#pragma unroll
            for (int i = 0; i < 4; i++)
#pragma unroll
                for (int j = 0; j < 2; j++)
                    wmma::mma_sync(acc[i][j], af[i], bfr[j], acc[i][j]);
        }
    }

#pragma unroll
    for (int i = 0; i < 4; i++)
#pragma unroll
        for (int j = 0; j < 2; j++) {
#pragma unroll
            for (int e = 0; e < acc[i][j].num_elements; e++)
                acc[i][j].x[e] *= 0.125f;
            wmma::store_matrix_sync(
                Cb + (long long)(m0 + wm * 64 + i * 16) * TT + n0 + wn * 32 + j * 16,
                acc[i][j], TT, wmma::mem_row_major);
        }
}

// =====================================================================
// bf16 WMMA PV: ctx[b,q,h*64+n] = P @ V.  128x64x32 tile, 8 warps
// (4 along M x 2 along N), warp tile 32x32.
// =====================================================================
__global__ void __launch_bounds__(256) bpv(
    const bf16* __restrict__ P, const bf16* __restrict__ V, float* __restrict__ ctx)
{
    const int z = blockIdx.y;
    const int b = z >> 3, h = z & 7;
    const bf16* Ab = P + (long long)z * TT * TT;
    const bf16* Bb = V + ((long long)b * TT) * DD + h * DHH;
    float* Cb = ctx + ((long long)b * TT) * DD + h * DHH;

    const int m0 = blockIdx.x * 128;

    __shared__ __align__(16) bf16 As[128][40];
    __shared__ __align__(16) bf16 Bs[32][72];

    const int tid  = threadIdx.x;
    const int warp = tid >> 5;
    const int wm   = warp & 3;      // 0..3 -> 32 rows
    const int wn   = warp >> 2;     // 0..1 -> 32 cols

    wmma::fragment<wmma::accumulator, 16, 16, 16, float> acc[2][2];
#pragma unroll
    for (int i = 0; i < 2; i++)
#pragma unroll
        for (int j = 0; j < 2; j++)
            wmma::fill_fragment(acc[i][j], 0.f);

    const int arow = tid >> 2, acg = (tid & 3) * 8;
    const int brow = tid >> 3, bcg = (tid & 7) * 8;

    for (int k0 = 0; k0 < TT; k0 += 32) {
        uint4 a0 = *(const uint4*)(Ab + (long long)(m0 + arow)      * TT + k0 + acg);
        uint4 a1 = *(const uint4*)(Ab + (long long)(m0 + arow + 64) * TT + k0 + acg);
        uint4 b0 = *(const uint4*)(Bb + (long long)(k0 + brow) * DD + bcg);
        __syncthreads();
        *(uint4*)&As[arow][acg]      = a0;
        *(uint4*)&As[arow + 64][acg] = a1;
        *(uint4*)&Bs[brow][bcg]      = b0;
        __syncthreads();
#pragma unroll
        for (int kk = 0; kk < 32; kk += 16) {
            wmma::fragment<wmma::matrix_a, 16, 16, 16, bf16, wmma::row_major> af[2];
            wmma::fragment<wmma::matrix_b, 16, 16, 16, bf16, wmma::row_major> bfr[2];
#pragma unroll
            for (int i = 0; i < 2; i++)
                wmma::load_matrix_sync(af[i], &As[wm * 32 + i * 16][kk], 40);
#pragma unroll
            for (int j = 0; j < 2; j++)
                wmma::load_matrix_sync(bfr[j], &Bs[kk][wn * 32 + j * 16], 72);
#pragma unroll
            for (int i = 0; i < 2; i++)
#pragma unroll
                for (int j = 0; j < 2; j++)
                    wmma::mma_sync(acc[i][j], af[i], bfr[j], acc[i][j]);
        }
    }

#pragma unroll
    for (int i = 0; i < 2; i++)
#pragma unroll
        for (int j = 0; j < 2; j++)
            wmma::store_matrix_sync(
                Cb + (long long)(m0 + wm * 32 + i * 16) * DD + wn * 32 + j * 16,
                acc[i][j], DD, wmma::mem_row_major);
}

// =====================================================================
// Row softmax over T=1024 (in place, fp32) + bf16 copy of probs.
// ids != null => block-diagonal window mask.
// =====================================================================
__global__ void __launch_bounds__(256) softmax_rows_k(float* __restrict__ S,
                                                      const int* __restrict__ ids,
                                                      bf16* __restrict__ Pbf)
{
    const long long r = blockIdx.x;
    const int q  = (int)(r & (TT - 1));
    const int bh = (int)(r >> 10);
    const int b  = bh >> 3;
    float* row = S + r * TT;
    bf16*  rbf = Pbf + r * TT;
    const int tid = threadIdx.x;

    __shared__ float sh[256];

    const float NEG = __int_as_float(0xff800000);
    const int idbase = b * TT;
    const int qid = ids ? ids[idbase + q] : 0;

    float v[4];
    float mx = -3.4e38f;
#pragma unroll
    for (int i = 0; i < 4; i++) {
        int k = tid + i * 256;
        float x = row[k];
        if (ids && ids[idbase + k] != qid) x = NEG;
        v[i] = x;
        mx = fmaxf(mx, x);
    }
    sh[tid] = mx; __syncthreads();
    for (int s = 128; s > 0; s >>= 1) { if (tid < s) sh[tid] = fmaxf(sh[tid], sh[tid + s]); __syncthreads(); }
    mx = sh[0]; __syncthreads();

    float e[4];
    float sum = 0.f;
#pragma unroll
    for (int i = 0; i < 4; i++) { e[i] = expf(v[i] - mx); sum += e[i]; }
    sh[tid] = sum; __syncthreads();
    for (int s = 128; s > 0; s >>= 1) { if (tid < s) sh[tid] += sh[tid + s]; __syncthreads(); }
    const float inv = 1.f / sh[0];

#pragma unroll
    for (int i = 0; i < 4; i++) {
        float p = e[i] * inv;
        row[tid + i * 256] = p;
        rbf[tid + i * 256] = __float2bfloat16(p);
    }
}

// column sum (double accum): w[b,k] = (1/H) sum_{h,q} P[b,h,q,k]
__global__ void __launch_bounds__(256) colsum_k(const float* __restrict__ P,
                                                float* __restrict__ w)
{
    const int b = blockIdx.x;
    const int k = blockIdx.y * 256 + threadIdx.x;
    const float* p = P + (long long)b * HH * TT * TT + k;
    double s0 = 0, s1 = 0, s2 = 0, s3 = 0;
    for (long long i = 0; i < (long long)HH * TT; i += 4) {
        s0 += (double)p[i * TT];
        s1 += (double)p[(i + 1) * TT];
        s2 += (double)p[(i + 2) * TT];
        s3 += (double)p[(i + 3) * TT];
    }
    w[b * TT + k] = (float)(((s0 + s1) + (s2 + s3)) * (1.0 / HH));
}

__global__ void __launch_bounds__(256) minmax_k(const float* __restrict__ w,
                                                float* __restrict__ mm)
{
    const int b = blockIdx.x, tid = threadIdx.x;
    __shared__ float smn[256], smx[256];
    float mn = 3.4e38f, mx = -3.4e38f;
    for (int t = tid; t < TT; t += 256) {
        float x = w[b * TT + t];
        mn = fminf(mn, x); mx = fmaxf(mx, x);
    }
    smn[tid] = mn; smx[tid] = mx; __syncthreads();
    for (int s = 128; s > 0; s >>= 1) {
        if (tid < s) { smn[tid] = fminf(smn[tid], smn[tid + s]); smx[tid] = fmaxf(smx[tid], smx[tid + s]); }
        __syncthreads();
    }
    if (tid == 0) { mm[b * 2] = smn[0]; mm[b * 2 + 1] = smx[0]; }
}

__global__ void winscan_k(const float* __restrict__ w, const float* __restrict__ mm,
                          int* __restrict__ ids)
{
    const int b = threadIdx.x;
    if (b >= BB) return;
    const float mn  = mm[b * 2];
    const float den = mm[b * 2 + 1] - mn + 1e-8f;
    const float* wb = w + b * TT;
    int* idb = ids + b * TT;

    bool cur = ((wb[0] - mn) / den) >= 0.5f;
    int start = 0, wid = 0;
    idb[0] = 0;
    for (int t = 1; t < TT; t++) {
        bool wt = ((wb[t] - mn) / den) >= 0.5f;
        if (wt != cur) {
            cur = wt;
            if (start + 1 != t) { start = t; wid++; }
        }
        idb[t] = wid;
    }
}

__global__ void __launch_bounds__(256) softmax1d_k(const float* __restrict__ w,
                                                   float* __restrict__ wl)
{
    const int b = blockIdx.x, tid = threadIdx.x;
    __shared__ float sh[256];
    float v[4];
    float mx = -3.4e38f;
#pragma unroll
    for (int i = 0; i < 4; i++) { v[i] = w[b * TT + tid + i * 256]; mx = fmaxf(mx, v[i]); }
    sh[tid] = mx; __syncthreads();
    for (int s = 128; s > 0; s >>= 1) { if (tid < s) sh[tid] = fmaxf(sh[tid], sh[tid + s]); __syncthreads(); }
    mx = sh[0]; __syncthreads();
    float e[4], sum = 0.f;
#pragma unroll
    for (int i = 0; i < 4; i++) { e[i] = expf(v[i] - mx); sum += e[i]; }
    sh[tid] = sum; __syncthreads();
    for (int s = 128; s > 0; s >>= 1) { if (tid < s) sh[tid] += sh[tid + s]; __syncthreads(); }
    const float inv = 1.f / sh[0];
#pragma unroll
    for (int i = 0; i < 4; i++) wl[b * TT + tid + i * 256] = e[i] * inv;
}

// in-place LayerNorm over D=512 + optional bf16 dual write
__global__ void __launch_bounds__(256) ln_k(float* __restrict__ X, bf16* __restrict__ Xbf)
{
    const long long r = blockIdx.x;
    float* row = X + r * DD;
    const int tid = threadIdx.x;
    __shared__ float sh[256];

    float x0 = row[tid], x1 = row[tid + 256];
    sh[tid] = x0 + x1; __syncthreads();
    for (int s = 128; s > 0; s >>= 1) { if (tid < s) sh[tid] += sh[tid + s]; __syncthreads(); }
    const float mean = sh[0] * (1.f / DD);
    __syncthreads();

    const float d0 = x0 - mean, d1 = x1 - mean;
    sh[tid] = d0 * d0 + d1 * d1; __syncthreads();
    for (int s = 128; s > 0; s >>= 1) { if (tid < s) sh[tid] += sh[tid + s]; __syncthreads(); }
    const float var = sh[0] * (1.f / DD);
    const float rs = 1.f / sqrtf(var + 1e-5f);
    const float y0 = d0 * rs, y1 = d1 * rs;
    row[tid] = y0;
    row[tid + 256] = y1;
    if (Xbf) {
        Xbf[r * DD + tid]       = __float2bfloat16(y0);
        Xbf[r * DD + tid + 256] = __float2bfloat16(y1);
    }
}

// float -> bf16 conversion, 4 elems/thread (n % 1024 == 0)
__global__ void __launch_bounds__(256) f2bf_k(const float* __restrict__ src,
                                              bf16* __restrict__ dst, long long n)
{
    const long long i = ((long long)blockIdx.x * 256 + threadIdx.x) * 4;
    if (i >= n) return;
    float4 v = *(const float4*)(src + i);
    __nv_bfloat162 p0, p1;
    p0.x = __float2bfloat16(v.x); p0.y = __float2bfloat16(v.y);
    p1.x = __float2bfloat16(v.z); p1.y = __float2bfloat16(v.w);
    *(__nv_bfloat162*)(dst + i)     = p0;
    *(__nv_bfloat162*)(dst + i + 2) = p1;
}

// out[:, 0:T, :] = 0 ; out[:, T:2T, :] = x
__global__ void __launch_bounds__(256) outinit_k(const float* __restrict__ x,
                                                 float* __restrict__ out)
{
    const long long idx = (long long)blockIdx.x * 256 + threadIdx.x;
    const int d = (int)(idx & (DD - 1));
    const long long rb = idx >> 9;
    const int r = (int)(rb & (2 * TT - 1));
    const int b = (int)(rb >> 11);
    out[idx] = (r < TT) ? 0.f : x[((long long)b * TT + (r - TT)) * DD + d];
}

// segmented pooling
__global__ void __launch_bounds__(512) pool_k(const float* __restrict__ outl,
                                              const float* __restrict__ wl,
                                              const int* __restrict__ ids,
                                              float* __restrict__ out)
{
    const int b = blockIdx.x, d = threadIdx.x;
    __shared__ int   sids[TT];
    __shared__ float swl[TT];
    for (int t = d; t < TT; t += 512) {
        sids[t] = ids[b * TT + t];
        swl[t]  = wl[b * TT + t];
    }
    __syncthreads();

    const float* xb = outl + (long long)b * TT * DD + d;
    float acc = 0.f;
    for (int t0 = 0; t0 < TT; t0 += 16) {
        float vals[16];
#pragma unroll
        for (int u = 0; u < 16; u++) vals[u] = xb[(long long)(t0 + u) * DD];
#pragma unroll
        for (int u = 0; u < 16; u++) {
            const int t = t0 + u;
            acc = fmaf(vals[u], swl[t], acc);
            const int curid = sids[t];
            const bool flush = (t == TT - 1) || (sids[t + 1] != curid);
            if (flush) {
                out[((long long)b * 2 * TT + curid) * DD + d] = acc;
                acc = 0.f;
            }
        }
    }
}

__global__ void __launch_bounds__(256) mapping_k(const int* __restrict__ ids,
                                                 float* __restrict__ out2)
{
    const long long idx = (long long)blockIdx.x * 256 + threadIdx.x;
    const int j = (int)(idx & (TT - 1));
    const long long wb = idx >> 10;
    const int wrow = (int)(wb & (TT - 1));
    const int b = (int)(wb >> 10);
    out2[idx] = (ids[b * TT + j] == wrow) ? 1.f : 0.f;
}

// =====================================================================
// host
// =====================================================================
extern "C" void kernel_launch(void* const* d_in, const int* in_sizes, int n_in,
                              void* d_out, int out_size)
{
    (void)in_sizes; (void)n_in; (void)out_size;
    const float* x       = (const float*)d_in[0];
    const float* v_qkv_w = (const float*)d_in[1];
    const float* v_out_w = (const float*)d_in[2];
    const float* v_w1    = (const float*)d_in[3];
    const float* v_w2    = (const float*)d_in[4];
    const float* l_qkv_w = (const float*)d_in[5];
    const float* l_out_w = (const float*)d_in[6];
    const float* l_w1    = (const float*)d_in[7];
    const float* l_w2    = (const float*)d_in[8];
    float* out = (float*)d_out;

    float *qkv, *scores, *ctx, *tmp, *ff, *outv, *outl, *w, *mm, *wl;
    int* ids;
    bf16 *wbf, *xbf, *qkvbf, *probsbf, *ctxbf, *tmpbf, *outvbf, *ffbf;
    cudaGetSymbolAddress((void**)&qkv,    g_qkv);
    cudaGetSymbolAddress((void**)&scores, g_scores);
    cudaGetSymbolAddress((void**)&ctx,    g_ctx);
    cudaGetSymbolAddress((void**)&tmp,    g_tmp);
    cudaGetSymbolAddress((void**)&ff,     g_ff);
    cudaGetSymbolAddress((void**)&outv,   g_outv);
    cudaGetSymbolAddress((void**)&outl,   g_outl);
    cudaGetSymbolAddress((void**)&w,      g_w);
    cudaGetSymbolAddress((void**)&mm,     g_mm);
    cudaGetSymbolAddress((void**)&ids,    g_ids);
    cudaGetSymbolAddress((void**)&wl,     g_wl);
    cudaGetSymbolAddress((void**)&wbf,    g_wbf);
    cudaGetSymbolAddress((void**)&xbf,    g_xbf);
    cudaGetSymbolAddress((void**)&qkvbf,  g_qkvbf);
    cudaGetSymbolAddress((void**)&probsbf,g_probsbf);
    cudaGetSymbolAddress((void**)&ctxbf,  g_ctxbf);
    cudaGetSymbolAddress((void**)&tmpbf,  g_tmpbf);
    cudaGetSymbolAddress((void**)&outvbf, g_outvbf);
    cudaGetSymbolAddress((void**)&ffbf,   g_ffbf);

    const dim3 blk(256);
    const long long sQKVw = (long long)DD * DD;
    const long long sQKVc = (long long)BT * DD;

    // ---- weight + input conversions ----
    auto cvt = [&](const float* s, bf16* d, long long n) {
        f2bf_k<<<(unsigned)((n + 1023) / 1024), blk>>>(s, d, n);
    };
    cvt(v_qkv_w, wbf + OFF_VQKV, 3LL * DD * DD);
    cvt(v_out_w, wbf + OFF_VOUT, (long long)DD * DD);
    cvt(v_w1,    wbf + OFF_VW1,  (long long)DD * FFD);
    cvt(v_w2,    wbf + OFF_VW2,  (long long)FFD * DD);
    cvt(l_qkv_w, wbf + OFF_LQKV, 3LL * DD * DD);
    cvt(l_out_w, wbf + OFF_LOUT, (long long)DD * DD);
    cvt(l_w1,    wbf + OFF_LW1,  (long long)DD * FFD);
    cvt(l_w2,    wbf + OFF_LW2,  (long long)FFD * DD);
    cvt(x, xbf, sQKVc);

    // ---------------- layer 1 (vanilla) ----------------
    // Q,K in fp32 (threshold-critical)
    sgemm64<<<dim3(DD / 64, BT / 64, 2), blk>>>(x, DD, 0, v_qkv_w, DD, sQKVw,
                                                qkv, DD, sQKVc, DD);
    // V in bf16
    bgemm_nn<<<dim3(DD / 128, BT / 128, 1), blk>>>(xbf, DD, 0,
                                                   wbf + OFF_VQKV + 2 * sQKVw, DD, 0,
                                                   qkv + 2 * sQKVc, DD, 0, nullptr, DD, 0);
    attn_scores_k<<<dim3(TT / 64, TT / 64, BHH), blk>>>(qkv, qkv + sQKVc, scores);
    softmax_rows_k<<<BHH * TT, blk>>>(scores, nullptr, probsbf);
    colsum_k<<<dim3(BB, TT / 256), blk>>>(scores, w);
    minmax_k<<<BB, blk>>>(w, mm);
    winscan_k<<<1, 32>>>(w, mm, ids);
    cvt(qkv + 2 * sQKVc, qkvbf + 2 * sQKVc, sQKVc);
    bpv<<<dim3(TT / 128, BHH), blk>>>(probsbf, qkvbf + 2 * sQKVc, ctx);
    cvt(ctx, ctxbf, sQKVc);
    bgemm_nn<<<dim3(DD / 128, BT / 128, 1), blk>>>(ctxbf, DD, 0, wbf + OFF_VOUT, DD, 0,
                                                   tmp, DD, 0, x, DD, 2);
    ln_k<<<BT, blk>>>(tmp, tmpbf);
    bgemm_nn<<<dim3(FFD / 128, BT / 128, 1), blk>>>(tmpbf, DD, 0, wbf + OFF_VW1, FFD, 0,
                                                    ff, FFD, 0, nullptr, DD, 1);
    cvt(ff, ffbf, (long long)BT * FFD);
    bgemm_nn<<<dim3(DD / 128, BT / 128, 1), blk>>>(ffbf, FFD, 0, wbf + OFF_VW2, DD, 0,
                                                   outv, DD, 0, tmp, FFD, 2);
    ln_k<<<BT, blk>>>(outv, outvbf);

    // ---------------- layer 2 (windowed, all bf16) ----------------
    bgemm_nn<<<dim3(DD / 128, BT / 128, 3), blk>>>(outvbf, DD, 0, wbf + OFF_LQKV, DD, sQKVw,
                                                   qkv, DD, sQKVc, nullptr, DD, 0);
    cvt(qkv, qkvbf, 3 * sQKVc);
    bscores<<<dim3(TT / 128, TT / 128, BHH), blk>>>(qkvbf, qkvbf + sQKVc, scores);
    softmax_rows_k<<<BHH * TT, blk>>>(scores, ids, probsbf);
    colsum_k<<<dim3(BB, TT / 256), blk>>>(scores, w);
    softmax1d_k<<<BB, blk>>>(w, wl);
    bpv<<<dim3(TT / 128, BHH), blk>>>(probsbf, qkvbf + 2 * sQKVc, ctx);
    cvt(ctx, ctxbf, sQKVc);
    bgemm_nn<<<dim3(DD / 128, BT / 128, 1), blk>>>(ctxbf, DD, 0, wbf + OFF_LOUT, DD, 0,
                                                   tmp, DD, 0, outv, DD, 2);
    ln_k<<<BT, blk>>>(tmp, tmpbf);
    bgemm_nn<<<dim3(FFD / 128, BT / 128, 1), blk>>>(tmpbf, DD, 0, wbf + OFF_LW1, FFD, 0,
                                                    ff, FFD, 0, nullptr, DD, 1);
    cvt(ff, ffbf, (long long)BT * FFD);
    bgemm_nn<<<dim3(DD / 128, BT / 128, 1), blk>>>(ffbf, FFD, 0, wbf + OFF_LW2, DD, 0,
                                                   outl, DD, 0, tmp, FFD, 2);
    ln_k<<<BT, blk>>>(outl, nullptr);

    // ---------------- outputs ----------------
    const long long n1 = (long long)BB * 2 * TT * DD;
    outinit_k<<<(unsigned)(n1 / 256), blk>>>(x, out);
    pool_k<<<BB, 512>>>(outl, wl, ids, out);
    mapping_k<<<(unsigned)(((long long)BB * TT * TT) / 256), blk>>>(ids, out + n1);
}